// round 10
// baseline (speedup 1.0000x reference)
#include <cuda_runtime.h>
#include <cstdint>

// RVQTokenizer encode: x [N,D] f32, codebooks [Q,K,D] f32.
// Output (mode 0): [codes as float (N*Q)] ++ [quantized f32 (N*D)].
//
// PROVEN bit-exact vs reference (R6/R7/R9, rel_err = 0.0):
//   norms : 16 strided fused-fmaf lanes (k mod 16), linear part fold,
//           shuffle-halves horizontal (c0+c2)+(c1+c3)
//   dot   : sequential ascending fused fmaf chain
//   d2    : fl( fl(S - 2*dot) + C ); argmin strict <, first index wins
//   state : q += cb[idx]; r = x - q (fp32 elementwise, __fadd_rn)
// DO NOT change that arithmetic. R10: occupancy-first restructuring —
//   1 row/thread, 256 threads/block, launch_bounds(256,2): ~25% occ,
//   register headroom for load pipelining; 4-code inner blocks keep
//   LDS:FFMA2 = 1:4 so the FMA pipe is the binder.

#define NROWS 262144
#define NQ    8
#define NK    1024
#define ND    64

#define TILE_K    128
#define CB_STRIDE 68
#define THREADS   256
#define MARGIN    2e-3f
#define NTILES    (NK / TILE_K)          // 8
#define NITER     (NQ * NTILES)          // 64

__device__ float g_q[(size_t)NROWS * ND];   // q accumulator scratch (64 MB)

union F2U { float2 f; unsigned long long u; };

__device__ __forceinline__ float2 ffma2(float2 a, float2 b, float2 c) {
    F2U A, B, C, D;
    A.f = a; B.f = b; C.f = c;
    asm("fma.rn.f32x2 %0, %1, %2, %3;" : "=l"(D.u) : "l"(A.u), "l"(B.u), "l"(C.u));
    return D.f;
}

__device__ __forceinline__ void cp_async16(unsigned int smem_addr, const void* gptr) {
    asm volatile("cp.async.cg.shared.global [%0], [%1], 16;"
                 :: "r"(smem_addr), "l"(gptr));
}

// Reference norm replica (PROVEN): LLVM VF=4 IC=4 strided lanes over 64 elems.
__device__ __forceinline__ float xla_rowsum_sq16(const float* __restrict__ v) {
    float a[16];
#pragma unroll
    for (int l = 0; l < 16; l++) a[l] = 0.0f;
#pragma unroll
    for (int j = 0; j < 4; j++)
#pragma unroll
        for (int l = 0; l < 16; l++) {
            float e = v[16 * j + l];
            a[l] = fmaf(e, e, a[l]);
        }
    float c[4];
#pragma unroll
    for (int l = 0; l < 4; l++) {
        float s = __fadd_rn(a[l], a[l + 4]);
        s = __fadd_rn(s, a[l + 8]);
        c[l] = __fadd_rn(s, a[l + 12]);
    }
    float h0 = __fadd_rn(c[0], c[2]);
    float h1 = __fadd_rn(c[1], c[3]);
    return __fadd_rn(h0, h1);
}

// Full-K reference-replica rescan (PROVEN). Residual re-derived from x/g_q.
__device__ __noinline__ int rescan_row_g(const float* __restrict__ x,
                                         int use_q, long long row,
                                         const float* __restrict__ cbj)
{
    const float* xr = x + row * ND;
    const float* qr = g_q + row * ND;
    float rs[ND];
#pragma unroll
    for (int k = 0; k < ND; k++)
        rs[k] = use_q ? __fadd_rn(xr[k], -qr[k]) : xr[k];

    float S = xla_rowsum_sq16(rs);

    float best = __int_as_float(0x7f800000);
    int bidx = 0;
    for (int c = 0; c < NK; c++) {
        const float* cp = cbj + (size_t)c * ND;
        float C = xla_rowsum_sq16(cp);
        float acc = 0.0f;
        for (int k = 0; k < ND; k++)
            acc = fmaf(rs[k], cp[k], acc);
        float B  = __fmul_rn(2.0f, acc);
        float t1 = __fadd_rn(S, -B);
        float d2 = __fadd_rn(t1, C);
        if (d2 < best) { best = d2; bidx = c; }
    }
    return bidx;
}

// mode 0: [codes as float] ++ [quantized]; mode 1: int codes; mode 2: quantized.
__global__ __launch_bounds__(THREADS, 2)
void rvq_kernel(const float* __restrict__ x,
                const float* __restrict__ cb,
                float* __restrict__ out,
                int mode)
{
    __shared__ __align__(16) float sh_cb[2][TILE_K * CB_STRIDE];
    __shared__ float sh_norm[2][TILE_K];

    const int t = threadIdx.x;
    const long long row = (long long)blockIdx.x * THREADS + t;

    // Residual in registers (stage 0: r = x).
    float2 rr[ND / 2];
    {
        const float4* x4p = (const float4*)(x + row * ND);
#pragma unroll
        for (int i = 0; i < ND / 4; i++) {
            float4 v = x4p[i];
            rr[2 * i]     = make_float2(v.x, v.y);
            rr[2 * i + 1] = make_float2(v.z, v.w);
        }
    }

    float* outq = (mode == 0) ? (out + (size_t)NROWS * NQ)
                              : ((mode == 2) ? out : nullptr);

    // cp.async mapping: tile = 2048 16B-chunks; 256 threads x 8 chunks.
    // chunk idx = i*256 + t; code = idx>>4 (i advances code by 16); d4 = idx&15.
    unsigned int sdst[2];
    {
        int code = t >> 4, d4 = t & 15;
        sdst[0] = (unsigned int)__cvta_generic_to_shared(
                      &sh_cb[0][code * CB_STRIDE + d4 * 4]);
        sdst[1] = (unsigned int)__cvta_generic_to_shared(
                      &sh_cb[1][code * CB_STRIDE + d4 * 4]);
    }

    // Prologue: prefetch iteration 0 (stage 0, tile 0) into buffer 0.
    {
        const float4* src = (const float4*)cb;
#pragma unroll
        for (int i = 0; i < 8; i++)
            cp_async16(sdst[0] + (unsigned int)(i * 16 * CB_STRIDE * 4),
                       src + i * THREADS + t);
        asm volatile("cp.async.commit_group;");
    }

    const float INF = __int_as_float(0x7f800000);
    float best_d = INF, sec_d = INF;
    int bidx = 0;
    const float* cbj = cb;

    for (int it = 0; it < NITER; ++it) {
        const int j    = it >> 3;
        const int tile = it & 7;
        const int buf  = it & 1;

        if (tile == 0) {
            best_d = INF; sec_d = INF; bidx = 0;
            cbj = cb + (size_t)j * NK * ND;
        }

        asm volatile("cp.async.wait_group 0;");
        __syncthreads();

        // Prefetch next tile into the other buffer (tiles are residual-indep).
        if (it + 1 < NITER) {
            int nj = (it + 1) >> 3, ntile = (it + 1) & 7;
            const float4* src = (const float4*)(cb + (size_t)nj * NK * ND
                                                + (size_t)ntile * TILE_K * ND);
#pragma unroll
            for (int i = 0; i < 8; i++)
                cp_async16(sdst[buf ^ 1] + (unsigned int)(i * 16 * CB_STRIDE * 4),
                           src + i * THREADS + t);
        }
        asm volatile("cp.async.commit_group;");

        // Fast per-code norm (fast-path ordering only): threads 0..127.
        if (t < TILE_K) {
            float s = 0.f;
            const float4* cp = (const float4*)&sh_cb[buf][t * CB_STRIDE];
#pragma unroll
            for (int i = 0; i < ND / 4; i++) {
                float4 v = cp[i];
                s = fmaf(v.x, v.x, s); s = fmaf(v.y, v.y, s);
                s = fmaf(v.z, v.z, s); s = fmaf(v.w, v.w, s);
            }
            sh_norm[buf][t] = s;
        }
        __syncthreads();

        // Score 128 codes: 4 codes x 1 row per block, LDS.128 broadcast.
        const float* shc = sh_cb[buf];
        const float* shn = sh_norm[buf];
        for (int c = 0; c < TILE_K; c += 4) {
            const float4* cp0 = (const float4*)&shc[c * CB_STRIDE];
            const float4* cp1 = (const float4*)&shc[(c + 1) * CB_STRIDE];
            const float4* cp2 = (const float4*)&shc[(c + 2) * CB_STRIDE];
            const float4* cp3 = (const float4*)&shc[(c + 3) * CB_STRIDE];
            float2 a0 = make_float2(0.f, 0.f), a1 = a0, a2 = a0, a3 = a0;
#pragma unroll
            for (int d = 0; d < ND / 4; d++) {
                float4 v0 = cp0[d];
                float4 v1 = cp1[d];
                float4 v2 = cp2[d];
                float4 v3 = cp3[d];
                float2 rl = rr[2 * d], rh = rr[2 * d + 1];
                a0 = ffma2(rl, make_float2(v0.x, v0.y), a0);
                a1 = ffma2(rl, make_float2(v1.x, v1.y), a1);
                a2 = ffma2(rl, make_float2(v2.x, v2.y), a2);
                a3 = ffma2(rl, make_float2(v3.x, v3.y), a3);
                a0 = ffma2(rh, make_float2(v0.z, v0.w), a0);
                a1 = ffma2(rh, make_float2(v1.z, v1.w), a1);
                a2 = ffma2(rh, make_float2(v2.z, v2.w), a2);
                a3 = ffma2(rh, make_float2(v3.z, v3.w), a3);
            }
            float d0 = shn[c]     - 2.f * (a0.x + a0.y);
            float d1 = shn[c + 1] - 2.f * (a1.x + a1.y);
            float d2 = shn[c + 2] - 2.f * (a2.x + a2.y);
            float d3 = shn[c + 3] - 2.f * (a3.x + a3.y);
            int ci = tile * TILE_K + c;
            if (d0 < best_d)      { sec_d = best_d; best_d = d0; bidx = ci; }
            else if (d0 < sec_d)  { sec_d = d0; }
            if (d1 < best_d)      { sec_d = best_d; best_d = d1; bidx = ci + 1; }
            else if (d1 < sec_d)  { sec_d = d1; }
            if (d2 < best_d)      { sec_d = best_d; best_d = d2; bidx = ci + 2; }
            else if (d2 < sec_d)  { sec_d = d2; }
            if (d3 < best_d)      { sec_d = best_d; best_d = d3; bidx = ci + 3; }
            else if (d3 < sec_d)  { sec_d = d3; }
        }

        if (tile == NTILES - 1) {
            // Near-tie: full-K reference-replica rescan (state from globals).
            if (sec_d - best_d < MARGIN) bidx = rescan_row_g(x, j > 0, row, cbj);

            // Bit-exact reference state update: q += cb[idx]; r = x - q.
            const float4* cv4 = (const float4*)(cbj + (size_t)bidx * ND);
            float4* q4p = (float4*)(g_q + row * ND);
            const float4* x4p = (const float4*)(x + row * ND);
#pragma unroll
            for (int i = 0; i < ND / 4; i++) {
                float4 c4 = cv4[i];
                float4 q4;
                if (j == 0) q4 = c4;
                else { float4 qo = q4p[i];
                       q4 = make_float4(__fadd_rn(qo.x, c4.x), __fadd_rn(qo.y, c4.y),
                                        __fadd_rn(qo.z, c4.z), __fadd_rn(qo.w, c4.w)); }
                q4p[i] = q4;
                float4 x4 = x4p[i];
                rr[2 * i]     = make_float2(__fadd_rn(x4.x, -q4.x), __fadd_rn(x4.y, -q4.y));
                rr[2 * i + 1] = make_float2(__fadd_rn(x4.z, -q4.z), __fadd_rn(x4.w, -q4.w));
                if (j == NQ - 1 && outq) ((float4*)(outq + row * ND))[i] = q4;
            }

            if (mode == 0)      out[row * NQ + j] = (float)bidx;
            else if (mode == 1) ((int*)out)[row * NQ + j] = bidx;
        }
    }
}

extern "C" void kernel_launch(void* const* d_in, const int* in_sizes, int n_in,
                              void* d_out, int out_size)
{
    const float* x  = (const float*)d_in[0];
    const float* cb = (const float*)d_in[1];
    if (n_in >= 2 && in_sizes[0] == NQ * NK * ND && in_sizes[1] == NROWS * ND) {
        cb = (const float*)d_in[0];
        x  = (const float*)d_in[1];
    }

    int mode = 0;
    if (out_size == NROWS * NQ)      mode = 1;
    else if (out_size == NROWS * ND) mode = 2;

    rvq_kernel<<<NROWS / THREADS, THREADS>>>(x, cb, (float*)d_out, mode);
}

// round 11
// speedup vs baseline: 1.2483x; 1.2483x over previous
#include <cuda_runtime.h>
#include <cstdint>

// RVQTokenizer encode: x [N,D] f32, codebooks [Q,K,D] f32.
// Output (mode 0): [codes as float (N*Q)] ++ [quantized f32 (N*D)].
//
// PROVEN bit-exact vs reference (R6/R7/R9/R10, rel_err = 0.0):
//   norms : 16 strided fused-fmaf lanes (k mod 16), linear part fold,
//           shuffle-halves horizontal (c0+c2)+(c1+c3)
//   dot   : sequential ascending fused fmaf chain
//   d2    : fl( fl(S - 2*dot) + C ); argmin strict <, first index wins
//   state : q += cb[idx]; r = x - q (fp32 elementwise, __fadd_rn)
// DO NOT change that arithmetic. R11: latency-oriented restructuring —
//   - explicit register double-buffer prefetch in the scoring loop
//     (cover the 29-cyc LDS latency ptxas won't hide under reg pressure)
//   - 4 codes x 2 rows per block: 8 independent FFMA2 chains
//   - codebook norms precomputed once in a tiny pre-kernel

#define NROWS 262144
#define NQ    8
#define NK    1024
#define ND    64

#define TILE_K    128
#define CB_STRIDE 68
#define THREADS   128
#define ROWS_PER_BLOCK (THREADS * 2)
#define MARGIN    2e-3f
#define NTILES    (NK / TILE_K)          // 8
#define NITER     (NQ * NTILES)          // 64

__device__ float g_q[(size_t)NROWS * ND];   // q accumulator scratch (64 MB)
__device__ float g_norm[NQ * NK];           // fast-path codebook norms

union F2U { float2 f; unsigned long long u; };

__device__ __forceinline__ float2 ffma2(float2 a, float2 b, float2 c) {
    F2U A, B, C, D;
    A.f = a; B.f = b; C.f = c;
    asm("fma.rn.f32x2 %0, %1, %2, %3;" : "=l"(D.u) : "l"(A.u), "l"(B.u), "l"(C.u));
    return D.f;
}

__device__ __forceinline__ void cp_async16(unsigned int smem_addr, const void* gptr) {
    asm volatile("cp.async.cg.shared.global [%0], [%1], 16;"
                 :: "r"(smem_addr), "l"(gptr));
}

// Reference norm replica (PROVEN): LLVM VF=4 IC=4 strided lanes over 64 elems.
__device__ __forceinline__ float xla_rowsum_sq16(const float* __restrict__ v) {
    float a[16];
#pragma unroll
    for (int l = 0; l < 16; l++) a[l] = 0.0f;
#pragma unroll
    for (int j = 0; j < 4; j++)
#pragma unroll
        for (int l = 0; l < 16; l++) {
            float e = v[16 * j + l];
            a[l] = fmaf(e, e, a[l]);
        }
    float c[4];
#pragma unroll
    for (int l = 0; l < 4; l++) {
        float s = __fadd_rn(a[l], a[l + 4]);
        s = __fadd_rn(s, a[l + 8]);
        c[l] = __fadd_rn(s, a[l + 12]);
    }
    float h0 = __fadd_rn(c[0], c[2]);
    float h1 = __fadd_rn(c[1], c[3]);
    return __fadd_rn(h0, h1);
}

// Full-K reference-replica rescan (PROVEN). Residual re-derived from x/g_q.
__device__ __noinline__ int rescan_row_g(const float* __restrict__ x,
                                         int use_q, long long row,
                                         const float* __restrict__ cbj)
{
    const float* xr = x + row * ND;
    const float* qr = g_q + row * ND;
    float rs[ND];
#pragma unroll
    for (int k = 0; k < ND; k++)
        rs[k] = use_q ? __fadd_rn(xr[k], -qr[k]) : xr[k];

    float S = xla_rowsum_sq16(rs);

    float best = __int_as_float(0x7f800000);
    int bidx = 0;
    for (int c = 0; c < NK; c++) {
        const float* cp = cbj + (size_t)c * ND;
        float C = xla_rowsum_sq16(cp);
        float acc = 0.0f;
        for (int k = 0; k < ND; k++)
            acc = fmaf(rs[k], cp[k], acc);
        float B  = __fmul_rn(2.0f, acc);
        float t1 = __fadd_rn(S, -B);
        float d2 = __fadd_rn(t1, C);
        if (d2 < best) { best = d2; bidx = c; }
    }
    return bidx;
}

// Pre-kernel: fast-path codebook norms (ordering heuristic only).
__global__ void norm_kernel(const float* __restrict__ cb) {
    int i = blockIdx.x * blockDim.x + threadIdx.x;   // 0 .. NQ*NK-1
    const float* cp = cb + (size_t)i * ND;
    float s = 0.f;
#pragma unroll
    for (int k = 0; k < ND; k++) s = fmaf(cp[k], cp[k], s);
    g_norm[i] = s;
}

// mode 0: [codes as float] ++ [quantized]; mode 1: int codes; mode 2: quantized.
__global__ __launch_bounds__(THREADS, 3)
void rvq_kernel(const float* __restrict__ x,
                const float* __restrict__ cb,
                float* __restrict__ out,
                int mode)
{
    __shared__ __align__(16) float sh_cb[2][TILE_K * CB_STRIDE];
    __shared__ __align__(16) float sh_norm[2][TILE_K];

    const int t = threadIdx.x;
    const long long row_a = (long long)blockIdx.x * ROWS_PER_BLOCK + t;
    const long long row_b = row_a + THREADS;

    float2 ra[ND / 2], rb[ND / 2];
    {
        const float4* xa4 = (const float4*)(x + row_a * ND);
        const float4* xb4 = (const float4*)(x + row_b * ND);
#pragma unroll
        for (int i = 0; i < ND / 4; i++) {
            float4 va = xa4[i];
            ra[2 * i]     = make_float2(va.x, va.y);
            ra[2 * i + 1] = make_float2(va.z, va.w);
            float4 vb = xb4[i];
            rb[2 * i]     = make_float2(vb.x, vb.y);
            rb[2 * i + 1] = make_float2(vb.z, vb.w);
        }
    }

    float* outq = (mode == 0) ? (out + (size_t)NROWS * NQ)
                              : ((mode == 2) ? out : nullptr);

    // cp.async mapping: tile = 2048 16B-chunks; 128 threads x 16 chunks.
    // chunk idx = i*128 + t; code = idx>>4 (i advances code by 8); d4 = idx&15.
    unsigned int sdst[2], ndst[2];
    {
        int code = t >> 4, d4 = t & 15;
        sdst[0] = (unsigned int)__cvta_generic_to_shared(
                      &sh_cb[0][code * CB_STRIDE + d4 * 4]);
        sdst[1] = (unsigned int)__cvta_generic_to_shared(
                      &sh_cb[1][code * CB_STRIDE + d4 * 4]);
        ndst[0] = (unsigned int)__cvta_generic_to_shared(&sh_norm[0][t * 4]);
        ndst[1] = (unsigned int)__cvta_generic_to_shared(&sh_norm[1][t * 4]);
    }

    // Prologue: prefetch iteration 0 (stage 0, tile 0) into buffer 0.
    {
        const float4* src = (const float4*)cb;
#pragma unroll
        for (int i = 0; i < 16; i++)
            cp_async16(sdst[0] + (unsigned int)(i * 8 * CB_STRIDE * 4),
                       src + i * THREADS + t);
        if (t < TILE_K / 4)
            cp_async16(ndst[0], g_norm + t * 4);
        asm volatile("cp.async.commit_group;");
    }

    const float INF = __int_as_float(0x7f800000);
    float best_a = INF, sec_a = INF, best_b = INF, sec_b = INF;
    int bia = 0, bib = 0;
    const float* cbj = cb;

    for (int it = 0; it < NITER; ++it) {
        const int j    = it >> 3;
        const int tile = it & 7;
        const int buf  = it & 1;

        if (tile == 0) {
            best_a = INF; sec_a = INF; best_b = INF; sec_b = INF;
            bia = 0; bib = 0;
            cbj = cb + (size_t)j * NK * ND;
        }

        // Wait for this buffer's copy; barrier means every warp has finished
        // scoring the *other* buffer (previous iteration) -> safe to refill it.
        asm volatile("cp.async.wait_group 0;");
        __syncthreads();

        if (it + 1 < NITER) {
            int nj = (it + 1) >> 3, ntile = (it + 1) & 7;
            const float4* src = (const float4*)(cb + (size_t)nj * NK * ND
                                                + (size_t)ntile * TILE_K * ND);
#pragma unroll
            for (int i = 0; i < 16; i++)
                cp_async16(sdst[buf ^ 1] + (unsigned int)(i * 8 * CB_STRIDE * 4),
                           src + i * THREADS + t);
            if (t < TILE_K / 4)
                cp_async16(ndst[buf ^ 1],
                           g_norm + nj * NK + ntile * TILE_K + t * 4);
        }
        asm volatile("cp.async.commit_group;");

        // Score 128 codes: 4 codes x 2 rows, register-pipelined LDS.128.
        const float* shc = sh_cb[buf];
        const float* shn = sh_norm[buf];
        for (int c = 0; c < TILE_K; c += 4) {
            const float4* p0 = (const float4*)&shc[c * CB_STRIDE];
            const float4* p1 = (const float4*)&shc[(c + 1) * CB_STRIDE];
            const float4* p2 = (const float4*)&shc[(c + 2) * CB_STRIDE];
            const float4* p3 = (const float4*)&shc[(c + 3) * CB_STRIDE];
            float4 n0 = p0[0], n1 = p1[0], n2 = p2[0], n3 = p3[0];
            float2 a0 = make_float2(0.f, 0.f), a1 = a0, a2 = a0, a3 = a0;
            float2 b0 = a0, b1 = a0, b2 = a0, b3 = a0;
#pragma unroll
            for (int d = 0; d < ND / 4; d++) {
                float4 v0 = n0, v1 = n1, v2 = n2, v3 = n3;
                if (d < ND / 4 - 1) {           // prefetch next iteration
                    n0 = p0[d + 1]; n1 = p1[d + 1];
                    n2 = p2[d + 1]; n3 = p3[d + 1];
                }
                float2 rl = ra[2 * d], rh = ra[2 * d + 1];
                float2 sl = rb[2 * d], sh = rb[2 * d + 1];
                a0 = ffma2(rl, make_float2(v0.x, v0.y), a0);
                a1 = ffma2(rl, make_float2(v1.x, v1.y), a1);
                a2 = ffma2(rl, make_float2(v2.x, v2.y), a2);
                a3 = ffma2(rl, make_float2(v3.x, v3.y), a3);
                b0 = ffma2(sl, make_float2(v0.x, v0.y), b0);
                b1 = ffma2(sl, make_float2(v1.x, v1.y), b1);
                b2 = ffma2(sl, make_float2(v2.x, v2.y), b2);
                b3 = ffma2(sl, make_float2(v3.x, v3.y), b3);
                a0 = ffma2(rh, make_float2(v0.z, v0.w), a0);
                a1 = ffma2(rh, make_float2(v1.z, v1.w), a1);
                a2 = ffma2(rh, make_float2(v2.z, v2.w), a2);
                a3 = ffma2(rh, make_float2(v3.z, v3.w), a3);
                b0 = ffma2(sh, make_float2(v0.z, v0.w), b0);
                b1 = ffma2(sh, make_float2(v1.z, v1.w), b1);
                b2 = ffma2(sh, make_float2(v2.z, v2.w), b2);
                b3 = ffma2(sh, make_float2(v3.z, v3.w), b3);
            }
            float m0 = shn[c], m1 = shn[c + 1], m2 = shn[c + 2], m3 = shn[c + 3];
            float da0 = m0 - 2.f * (a0.x + a0.y);
            float da1 = m1 - 2.f * (a1.x + a1.y);
            float da2 = m2 - 2.f * (a2.x + a2.y);
            float da3 = m3 - 2.f * (a3.x + a3.y);
            float db0 = m0 - 2.f * (b0.x + b0.y);
            float db1 = m1 - 2.f * (b1.x + b1.y);
            float db2 = m2 - 2.f * (b2.x + b2.y);
            float db3 = m3 - 2.f * (b3.x + b3.y);
            int ci = tile * TILE_K + c;
            if (da0 < best_a)      { sec_a = best_a; best_a = da0; bia = ci; }
            else if (da0 < sec_a)  { sec_a = da0; }
            if (da1 < best_a)      { sec_a = best_a; best_a = da1; bia = ci + 1; }
            else if (da1 < sec_a)  { sec_a = da1; }
            if (da2 < best_a)      { sec_a = best_a; best_a = da2; bia = ci + 2; }
            else if (da2 < sec_a)  { sec_a = da2; }
            if (da3 < best_a)      { sec_a = best_a; best_a = da3; bia = ci + 3; }
            else if (da3 < sec_a)  { sec_a = da3; }
            if (db0 < best_b)      { sec_b = best_b; best_b = db0; bib = ci; }
            else if (db0 < sec_b)  { sec_b = db0; }
            if (db1 < best_b)      { sec_b = best_b; best_b = db1; bib = ci + 1; }
            else if (db1 < sec_b)  { sec_b = db1; }
            if (db2 < best_b)      { sec_b = best_b; best_b = db2; bib = ci + 2; }
            else if (db2 < sec_b)  { sec_b = db2; }
            if (db3 < best_b)      { sec_b = best_b; best_b = db3; bib = ci + 3; }
            else if (db3 < sec_b)  { sec_b = db3; }
        }

        if (tile == NTILES - 1) {
            // Near-tie: full-K reference-replica rescan (state from globals).
            if (sec_a - best_a < MARGIN) bia = rescan_row_g(x, j > 0, row_a, cbj);
            if (sec_b - best_b < MARGIN) bib = rescan_row_g(x, j > 0, row_b, cbj);

            // Bit-exact reference state update: q += cb[idx]; r = x - q.
            const float4* ca  = (const float4*)(cbj + (size_t)bia * ND);
            const float4* cbv = (const float4*)(cbj + (size_t)bib * ND);
            float4* qa = (float4*)(g_q + row_a * ND);
            float4* qb = (float4*)(g_q + row_b * ND);
            const float4* xa4 = (const float4*)(x + row_a * ND);
            const float4* xb4 = (const float4*)(x + row_b * ND);
#pragma unroll
            for (int i = 0; i < ND / 4; i++) {
                float4 c4 = ca[i];
                float4 q4;
                if (j == 0) q4 = c4;
                else { float4 qo = qa[i];
                       q4 = make_float4(__fadd_rn(qo.x, c4.x), __fadd_rn(qo.y, c4.y),
                                        __fadd_rn(qo.z, c4.z), __fadd_rn(qo.w, c4.w)); }
                qa[i] = q4;
                float4 x4 = xa4[i];
                ra[2 * i]     = make_float2(__fadd_rn(x4.x, -q4.x), __fadd_rn(x4.y, -q4.y));
                ra[2 * i + 1] = make_float2(__fadd_rn(x4.z, -q4.z), __fadd_rn(x4.w, -q4.w));
                if (j == NQ - 1 && outq) ((float4*)(outq + row_a * ND))[i] = q4;

                float4 d4 = cbv[i];
                float4 p4;
                if (j == 0) p4 = d4;
                else { float4 qo = qb[i];
                       p4 = make_float4(__fadd_rn(qo.x, d4.x), __fadd_rn(qo.y, d4.y),
                                        __fadd_rn(qo.z, d4.z), __fadd_rn(qo.w, d4.w)); }
                qb[i] = p4;
                float4 y4 = xb4[i];
                rb[2 * i]     = make_float2(__fadd_rn(y4.x, -p4.x), __fadd_rn(y4.y, -p4.y));
                rb[2 * i + 1] = make_float2(__fadd_rn(y4.z, -p4.z), __fadd_rn(y4.w, -p4.w));
                if (j == NQ - 1 && outq) ((float4*)(outq + row_b * ND))[i] = p4;
            }

            if (mode == 0) {
                out[row_a * NQ + j] = (float)bia;
                out[row_b * NQ + j] = (float)bib;
            } else if (mode == 1) {
                ((int*)out)[row_a * NQ + j] = bia;
                ((int*)out)[row_b * NQ + j] = bib;
            }
        }
    }
}

extern "C" void kernel_launch(void* const* d_in, const int* in_sizes, int n_in,
                              void* d_out, int out_size)
{
    const float* x  = (const float*)d_in[0];
    const float* cb = (const float*)d_in[1];
    if (n_in >= 2 && in_sizes[0] == NQ * NK * ND && in_sizes[1] == NROWS * ND) {
        cb = (const float*)d_in[0];
        x  = (const float*)d_in[1];
    }

    int mode = 0;
    if (out_size == NROWS * NQ)      mode = 1;
    else if (out_size == NROWS * ND) mode = 2;

    norm_kernel<<<(NQ * NK) / 256, 256>>>(cb);
    rvq_kernel<<<NROWS / ROWS_PER_BLOCK, THREADS>>>(x, cb, (float*)d_out, mode);
}

// round 13
// speedup vs baseline: 3.0469x; 2.4409x over previous
#include <cuda_runtime.h>
#include <cuda_bf16.h>
#include <cstdint>

// RVQTokenizer encode via mma.sync (HMMA, compute_103-safe) bf16-split fast path.
//   x [N,D] f32, codebooks [Q,K,D] f32.
// Output (mode 0): [codes as float (N*Q)] ++ [quantized f32 (N*D)].
//
// PROVEN bit-exact decision machinery (R6..R11, rel_err = 0.0) — UNCHANGED:
//   norms : 16 strided fused-fmaf lanes, linear fold, shuffle-halves horiz
//   dot   : sequential ascending fused fmaf chain
//   d2    : fl( fl(S - 2*dot) + C ); argmin strict <, first index wins
//   state : q += cb[idx]; r = x - q (fp32 elementwise, __fadd_rn)
// Fast path: D = (Ah+Al)(Bh+Bl) minus lo*lo, mma.m16n8k16 bf16 f32-accum,
// |d2_fast - d2_ref| ~1e-4 << MARGIN; near-ties -> exact warp rescan.

#define NROWS 262144
#define NQ    8
#define NK    1024
#define ND    64
#define THREADS      256
#define ROWS_PER_CTA 128
#define TILE_N       128
#define NTILES       8
#define MARGIN       2e-3f

#define ASTRIDE 144              // bytes per 64-bf16 row (72 bf16, conflict-free)

// smem layout (bytes from aligned base)
#define SM_A_HI  0
#define SM_A_LO  18432
#define SM_B     36864           // [buf][split] 4 x 18432
#define SM_SN    110592         // [buf] 2 x 512 (tile norms f32)
#define SM_CNT   111616
#define SM_ROWS  111680         // 128 ints
#define SM_BIDX  112192         // 128 ints
#define SMEM_REQ (112704 + 1024)

__device__ float g_q[(size_t)NROWS * ND];          // PROVEN q state (64 MB)
__device__ float g_norm[NQ * NK];
__device__ __nv_bfloat16 g_cbh[(size_t)NQ * NK * ND];
__device__ __nv_bfloat16 g_cbl[(size_t)NQ * NK * ND];

__device__ __forceinline__ void cp_async16(uint32_t dst, const void* src) {
    asm volatile("cp.async.cg.shared.global [%0], [%1], 16;"
                 :: "r"(dst), "l"(src));
}

static __device__ __forceinline__ uint32_t smem_u32(const void* p) {
    uint32_t a;
    asm("{ .reg .u64 t; cvta.to.shared.u64 t, %1; cvt.u32.u64 %0, t; }"
        : "=r"(a) : "l"(p));
    return a;
}

__device__ __forceinline__ void mma16816(float& c0, float& c1, float& c2, float& c3,
                                         uint32_t a0, uint32_t a1, uint32_t a2,
                                         uint32_t a3, uint32_t b0, uint32_t b1) {
    asm volatile(
        "mma.sync.aligned.m16n8k16.row.col.f32.bf16.bf16.f32 "
        "{%0,%1,%2,%3}, {%4,%5,%6,%7}, {%8,%9}, {%0,%1,%2,%3};"
        : "+f"(c0), "+f"(c1), "+f"(c2), "+f"(c3)
        : "r"(a0), "r"(a1), "r"(a2), "r"(a3), "r"(b0), "r"(b1));
}

// ---------- PROVEN exact-arithmetic pieces (DO NOT CHANGE) ----------
__device__ __forceinline__ float xla_rowsum_sq16(const float* __restrict__ v) {
    float a[16];
#pragma unroll
    for (int l = 0; l < 16; l++) a[l] = 0.0f;
#pragma unroll
    for (int j = 0; j < 4; j++)
#pragma unroll
        for (int l = 0; l < 16; l++) {
            float e = v[16 * j + l];
            a[l] = fmaf(e, e, a[l]);
        }
    float c[4];
#pragma unroll
    for (int l = 0; l < 4; l++) {
        float s = __fadd_rn(a[l], a[l + 4]);
        s = __fadd_rn(s, a[l + 8]);
        c[l] = __fadd_rn(s, a[l + 12]);
    }
    return __fadd_rn(__fadd_rn(c[0], c[2]), __fadd_rn(c[1], c[3]));
}

__device__ __noinline__ int warp_rescan(const float* __restrict__ x, int use_q,
                                        long long row,
                                        const float* __restrict__ cbj, int lane)
{
    const float* xr = x + row * ND;
    const float* qr = g_q + row * ND;
    float rs[ND];
#pragma unroll
    for (int k = 0; k < ND; k++)
        rs[k] = use_q ? __fadd_rn(xr[k], -qr[k]) : xr[k];
    float S = xla_rowsum_sq16(rs);

    float best = __int_as_float(0x7f800000);
    int bi = NK;
    for (int base = 0; base < NK; base += 32) {
        int c = base + lane;
        const float* cp = cbj + (size_t)c * ND;
        float C = xla_rowsum_sq16(cp);
        float acc = 0.0f;
        for (int k = 0; k < ND; k++)
            acc = fmaf(rs[k], cp[k], acc);
        float B  = __fmul_rn(2.0f, acc);
        float t1 = __fadd_rn(S, -B);
        float d2 = __fadd_rn(t1, C);
        if (d2 < best) { best = d2; bi = c; }
    }
#pragma unroll
    for (int off = 16; off >= 1; off >>= 1) {
        float ob = __shfl_down_sync(0xffffffff, best, off);
        int   oi = __shfl_down_sync(0xffffffff, bi, off);
        if (ob < best || (ob == best && oi < bi)) { best = ob; bi = oi; }
    }
    return __shfl_sync(0xffffffff, bi, 0);
}
// --------------------------------------------------------------------

__global__ void prep_kernel(const float* __restrict__ cb) {
    int i = blockIdx.x * blockDim.x + threadIdx.x;
    const float* cp = cb + (size_t)i * ND;
    float s = 0.f;
#pragma unroll
    for (int k = 0; k < ND; k++) s = fmaf(cp[k], cp[k], s);
    g_norm[i] = s;
#pragma unroll
    for (int k = 0; k < ND; k++) {
        float v = cp[k];
        __nv_bfloat16 h = __float2bfloat16(v);
        g_cbh[(size_t)i * ND + k] = h;
        g_cbl[(size_t)i * ND + k] = __float2bfloat16(v - __bfloat162float(h));
    }
}

#define UPD2(bst, sc, bi, d, ci) \
    do { if ((d) < (bst)) { sc = bst; bst = (d); bi = (ci); } \
         else if ((d) < (sc)) { sc = (d); } } while (0)

__global__ __launch_bounds__(THREADS)
void rvq_mma_kernel(const float* __restrict__ x,
                    const float* __restrict__ cb,
                    float* __restrict__ out, int mode)
{
    extern __shared__ char smem_raw[];
    char* smem = (char*)(((uintptr_t)smem_raw + 1023) & ~(uintptr_t)1023);
    const uint32_t sb = smem_u32(smem);

    const int t = threadIdx.x, wid = t >> 5, lane = t & 31;
    const int lq = lane >> 2, lr = lane & 3;      // quad id / quad lane
    const long long row0 = (long long)blockIdx.x * ROWS_PER_CTA;
    float* outq = (mode == 0) ? (out + (size_t)NROWS * NQ)
                              : ((mode == 2) ? out : nullptr);

    int* s_cnt  = (int*)(smem + SM_CNT);
    int* s_rows = (int*)(smem + SM_ROWS);
    int* s_bidx = (int*)(smem + SM_BIDX);

    for (int j = 0; j < NQ; j++) {
        const float* cbj = cb + (size_t)j * NK * ND;

        // ---- A convert: r = x - q (f32, PROVEN ops) -> bf16 hi/lo smem ----
        {
            int m = t >> 1, h = t & 1;
            const float4* xp = (const float4*)(x + (row0 + m) * ND) + h * 8;
            const float4* qp = (const float4*)(g_q + (row0 + m) * ND) + h * 8;
#pragma unroll
            for (int i = 0; i < 8; i++) {
                float4 xv = xp[i];
                float4 r;
                if (j == 0) r = xv;
                else {
                    float4 qv = qp[i];
                    r = make_float4(__fadd_rn(xv.x, -qv.x), __fadd_rn(xv.y, -qv.y),
                                    __fadd_rn(xv.z, -qv.z), __fadd_rn(xv.w, -qv.w));
                }
                __nv_bfloat162 h01 = __floats2bfloat162_rn(r.x, r.y);
                __nv_bfloat162 h23 = __floats2bfloat162_rn(r.z, r.w);
                float2 f01 = __bfloat1622float2(h01);
                float2 f23 = __bfloat1622float2(h23);
                __nv_bfloat162 l01 = __floats2bfloat162_rn(r.x - f01.x, r.y - f01.y);
                __nv_bfloat162 l23 = __floats2bfloat162_rn(r.z - f23.x, r.w - f23.y);
                uint32_t off = (uint32_t)(m * ASTRIDE + h * 64 + i * 8);
                *(uint2*)(smem + SM_A_HI + off) =
                    make_uint2(*(uint32_t*)&h01, *(uint32_t*)&h23);
                *(uint2*)(smem + SM_A_LO + off) =
                    make_uint2(*(uint32_t*)&l01, *(uint32_t*)&l23);
            }
        }
        if (t == 0) *s_cnt = 0;
        __syncthreads();

        // ---- A fragments into registers (persist across all 8 tiles) ----
        uint32_t ah[4][4], al[4][4];
        {
            int r0 = wid * 16 + lq;
            uint32_t base = (uint32_t)(r0 * ASTRIDE + lr * 4);
#pragma unroll
            for (int kc = 0; kc < 4; kc++) {
                uint32_t o = base + kc * 32;
                ah[kc][0] = *(const uint32_t*)(smem + SM_A_HI + o);
                ah[kc][1] = *(const uint32_t*)(smem + SM_A_HI + o + 8 * ASTRIDE);
                ah[kc][2] = *(const uint32_t*)(smem + SM_A_HI + o + 16);
                ah[kc][3] = *(const uint32_t*)(smem + SM_A_HI + o + 8 * ASTRIDE + 16);
                al[kc][0] = *(const uint32_t*)(smem + SM_A_LO + o);
                al[kc][1] = *(const uint32_t*)(smem + SM_A_LO + o + 8 * ASTRIDE);
                al[kc][2] = *(const uint32_t*)(smem + SM_A_LO + o + 16);
                al[kc][3] = *(const uint32_t*)(smem + SM_A_LO + o + 8 * ASTRIDE + 16);
            }
        }

        // ---- Prologue: B tile 0 (hi+lo) + norms into buf 0 ----
        {
            const __nv_bfloat16* sh = g_cbh + ((size_t)j * NK) * ND;
            const __nv_bfloat16* sl = g_cbl + ((size_t)j * NK) * ND;
#pragma unroll
            for (int i = 0; i < 4; i++) {
                int id = i * 256 + t, code = id >> 3, c8 = id & 7;
                uint32_t off = (uint32_t)(code * ASTRIDE + c8 * 16);
                cp_async16(sb + SM_B + off, sh + code * ND + c8 * 8);
                cp_async16(sb + SM_B + 18432 + off, sl + code * ND + c8 * 8);
            }
            if (t < 32)
                cp_async16(sb + SM_SN + t * 16, g_norm + j * NK + t * 4);
            asm volatile("cp.async.commit_group;" ::: "memory");
        }

        const float INF = __int_as_float(0x7f800000);
        float bA = INF, sA = INF, bB = INF, sB = INF;
        int iA = 0, iB = 0;

        // ---- tile loop ----
        for (int it = 0; it < NTILES; ++it) {
            const int buf = it & 1;
            asm volatile("cp.async.wait_group 0;" ::: "memory");
            __syncthreads();

            if (it + 1 < NTILES) {   // prefetch next tile into other buffer
                int nb = (it + 1) & 1;
                const __nv_bfloat16* sh =
                    g_cbh + ((size_t)j * NK + (it + 1) * TILE_N) * ND;
                const __nv_bfloat16* sl =
                    g_cbl + ((size_t)j * NK + (it + 1) * TILE_N) * ND;
#pragma unroll
                for (int i = 0; i < 4; i++) {
                    int id = i * 256 + t, code = id >> 3, c8 = id & 7;
                    uint32_t off = (uint32_t)(code * ASTRIDE + c8 * 16);
                    cp_async16(sb + SM_B + (uint32_t)(nb * 2) * 18432 + off,
                               sh + code * ND + c8 * 8);
                    cp_async16(sb + SM_B + (uint32_t)(nb * 2 + 1) * 18432 + off,
                               sl + code * ND + c8 * 8);
                }
                if (t < 32)
                    cp_async16(sb + SM_SN + nb * 512 + t * 16,
                               g_norm + j * NK + (it + 1) * TILE_N + t * 4);
            }
            asm volatile("cp.async.commit_group;" ::: "memory");

            const char* bh_p = smem + SM_B + (size_t)(buf * 2) * 18432;
            const char* bl_p = smem + SM_B + (size_t)(buf * 2 + 1) * 18432;
            const float* sn  = (const float*)(smem + SM_SN + buf * 512);

#pragma unroll
            for (int nb = 0; nb < 16; nb++) {
                float c0 = 0.f, c1 = 0.f, c2 = 0.f, c3 = 0.f;
                uint32_t bo = (uint32_t)((nb * 8 + lq) * ASTRIDE + lr * 4);
#pragma unroll
                for (int kc = 0; kc < 4; kc++) {
                    uint32_t o = bo + kc * 32;
                    uint32_t bh0 = *(const uint32_t*)(bh_p + o);
                    uint32_t bh1 = *(const uint32_t*)(bh_p + o + 16);
                    uint32_t bl0 = *(const uint32_t*)(bl_p + o);
                    uint32_t bl1 = *(const uint32_t*)(bl_p + o + 16);
                    mma16816(c0, c1, c2, c3, ah[kc][0], ah[kc][1], ah[kc][2],
                             ah[kc][3], bh0, bh1);
                    mma16816(c0, c1, c2, c3, ah[kc][0], ah[kc][1], ah[kc][2],
                             ah[kc][3], bl0, bl1);
                    mma16816(c0, c1, c2, c3, al[kc][0], al[kc][1], al[kc][2],
                             al[kc][3], bh0, bh1);
                }
                int cc = nb * 8 + lr * 2;
                float2 nv = *(const float2*)(sn + cc);
                int ci = it * TILE_N + cc;
                UPD2(bA, sA, iA, fmaf(-2.f, c0, nv.x), ci);
                UPD2(bA, sA, iA, fmaf(-2.f, c1, nv.y), ci + 1);
                UPD2(bB, sB, iB, fmaf(-2.f, c2, nv.x), ci);
                UPD2(bB, sB, iB, fmaf(-2.f, c3, nv.y), ci + 1);
            }
        }

        // ---- quad-lane top-2 merge (rows lq and lq+8 of this warp) ----
#pragma unroll
        for (int msk = 1; msk <= 2; msk <<= 1) {
            float ob = __shfl_xor_sync(0xffffffff, bA, msk);
            int   oi = __shfl_xor_sync(0xffffffff, iA, msk);
            float os = __shfl_xor_sync(0xffffffff, sA, msk);
            if (ob < bA) { sA = fminf(bA, os); bA = ob; iA = oi; }
            else         { sA = fminf(sA, ob); }
            ob = __shfl_xor_sync(0xffffffff, bB, msk);
            oi = __shfl_xor_sync(0xffffffff, iB, msk);
            os = __shfl_xor_sync(0xffffffff, sB, msk);
            if (ob < bB) { sB = fminf(bB, os); bB = ob; iB = oi; }
            else         { sB = fminf(sB, ob); }
        }
        if (lr == 0) {
            int m0 = wid * 16 + lq;
            s_bidx[m0] = iA;
            if (sA - bA < MARGIN) { int p = atomicAdd(s_cnt, 1); s_rows[p] = m0; }
            s_bidx[m0 + 8] = iB;
            if (sB - bB < MARGIN) { int p = atomicAdd(s_cnt, 1); s_rows[p] = m0 + 8; }
        }
        __syncthreads();

        // ---- near-ties: warp-cooperative exact rescan (PROVEN) ----
        int cnt = *s_cnt;
        for (int e = wid; e < cnt; e += 8) {
            int m = s_rows[e];
            int r = warp_rescan(x, j > 0, row0 + m, cbj, lane);
            if (lane == 0) s_bidx[m] = r;
        }
        __syncthreads();

        // ---- bit-exact state update + emission (PROVEN) ----
        {
            int m = t >> 1, h = t & 1;
            long long rg = row0 + m;
            int ci = s_bidx[m];
            const float4* cp = (const float4*)(cbj + (size_t)ci * ND) + h * 8;
            float4* qp = (float4*)(g_q + rg * ND) + h * 8;
#pragma unroll
            for (int i = 0; i < 8; i++) {
                float4 c4 = cp[i];
                float4 q4;
                if (j == 0) q4 = c4;
                else {
                    float4 qo = qp[i];
                    q4 = make_float4(__fadd_rn(qo.x, c4.x), __fadd_rn(qo.y, c4.y),
                                     __fadd_rn(qo.z, c4.z), __fadd_rn(qo.w, c4.w));
                }
                qp[i] = q4;
                if (j == NQ - 1 && outq)
                    (((float4*)(outq + rg * ND)) + h * 8)[i] = q4;
            }
            if (h == 0) {
                if (mode == 0)      out[rg * NQ + j] = (float)ci;
                else if (mode == 1) ((int*)out)[rg * NQ + j] = ci;
            }
        }
        __syncthreads();
    }
}

extern "C" void kernel_launch(void* const* d_in, const int* in_sizes, int n_in,
                              void* d_out, int out_size)
{
    const float* x  = (const float*)d_in[0];
    const float* cb = (const float*)d_in[1];
    if (n_in >= 2 && in_sizes[0] == NQ * NK * ND && in_sizes[1] == NROWS * ND) {
        cb = (const float*)d_in[0];
        x  = (const float*)d_in[1];
    }
    int mode = 0;
    if (out_size == NROWS * NQ)      mode = 1;
    else if (out_size == NROWS * ND) mode = 2;

    cudaFuncSetAttribute(rvq_mma_kernel,
                         cudaFuncAttributeMaxDynamicSharedMemorySize, SMEM_REQ);
    prep_kernel<<<(NQ * NK) / 256, 256>>>(cb);
    rvq_mma_kernel<<<NROWS / ROWS_PER_CTA, THREADS, SMEM_REQ>>>(
        x, cb, (float*)d_out, mode);
}

// round 14
// speedup vs baseline: 3.2312x; 1.0605x over previous
#include <cuda_runtime.h>
#include <cuda_bf16.h>
#include <cstdint>

// RVQTokenizer encode via mma.sync (HMMA) bf16-split fast path. R14 = R13 +
// ILP-2 accumulator interleave (2 independent MMA chains per warp).
//
// PROVEN bit-exact decision machinery (R6..R13, rel_err = 0.0) — UNCHANGED:
//   norms : 16 strided fused-fmaf lanes, linear fold, shuffle-halves horiz
//   dot   : sequential ascending fused fmaf chain
//   d2    : fl( fl(S - 2*dot) + C ); argmin strict <, first index wins
//   state : q += cb[idx]; r = x - q (fp32 elementwise, __fadd_rn)
// Fast path: D = AhBh + AhBl + AlBh (bf16 m16n8k16, f32 accum);
// |d2_fast - d2_ref| ~1e-4 << MARGIN; near-ties -> exact warp rescan.

#define NROWS 262144
#define NQ    8
#define NK    1024
#define ND    64
#define THREADS      256
#define ROWS_PER_CTA 128
#define TILE_N       128
#define NTILES       8
#define MARGIN       2e-3f

#define ASTRIDE 144

#define SM_A_HI  0
#define SM_A_LO  18432
#define SM_B     36864
#define SM_SN    110592
#define SM_CNT   111616
#define SM_ROWS  111680
#define SM_BIDX  112192
#define SMEM_REQ (112704 + 1024)

__device__ float g_q[(size_t)NROWS * ND];
__device__ float g_norm[NQ * NK];
__device__ __nv_bfloat16 g_cbh[(size_t)NQ * NK * ND];
__device__ __nv_bfloat16 g_cbl[(size_t)NQ * NK * ND];

__device__ __forceinline__ void cp_async16(uint32_t dst, const void* src) {
    asm volatile("cp.async.cg.shared.global [%0], [%1], 16;"
                 :: "r"(dst), "l"(src));
}

static __device__ __forceinline__ uint32_t smem_u32(const void* p) {
    uint32_t a;
    asm("{ .reg .u64 t; cvta.to.shared.u64 t, %1; cvt.u32.u64 %0, t; }"
        : "=r"(a) : "l"(p));
    return a;
}

__device__ __forceinline__ void mma16816(float& c0, float& c1, float& c2, float& c3,
                                         uint32_t a0, uint32_t a1, uint32_t a2,
                                         uint32_t a3, uint32_t b0, uint32_t b1) {
    asm volatile(
        "mma.sync.aligned.m16n8k16.row.col.f32.bf16.bf16.f32 "
        "{%0,%1,%2,%3}, {%4,%5,%6,%7}, {%8,%9}, {%0,%1,%2,%3};"
        : "+f"(c0), "+f"(c1), "+f"(c2), "+f"(c3)
        : "r"(a0), "r"(a1), "r"(a2), "r"(a3), "r"(b0), "r"(b1));
}

// ---------- PROVEN exact-arithmetic pieces (DO NOT CHANGE) ----------
__device__ __forceinline__ float xla_rowsum_sq16(const float* __restrict__ v) {
    float a[16];
#pragma unroll
    for (int l = 0; l < 16; l++) a[l] = 0.0f;
#pragma unroll
    for (int j = 0; j < 4; j++)
#pragma unroll
        for (int l = 0; l < 16; l++) {
            float e = v[16 * j + l];
            a[l] = fmaf(e, e, a[l]);
        }
    float c[4];
#pragma unroll
    for (int l = 0; l < 4; l++) {
        float s = __fadd_rn(a[l], a[l + 4]);
        s = __fadd_rn(s, a[l + 8]);
        c[l] = __fadd_rn(s, a[l + 12]);
    }
    return __fadd_rn(__fadd_rn(c[0], c[2]), __fadd_rn(c[1], c[3]));
}

__device__ __noinline__ int warp_rescan(const float* __restrict__ x, int use_q,
                                        long long row,
                                        const float* __restrict__ cbj, int lane)
{
    const float* xr = x + row * ND;
    const float* qr = g_q + row * ND;
    float rs[ND];
#pragma unroll
    for (int k = 0; k < ND; k++)
        rs[k] = use_q ? __fadd_rn(xr[k], -qr[k]) : xr[k];
    float S = xla_rowsum_sq16(rs);

    float best = __int_as_float(0x7f800000);
    int bi = NK;
    for (int base = 0; base < NK; base += 32) {
        int c = base + lane;
        const float* cp = cbj + (size_t)c * ND;
        float C = xla_rowsum_sq16(cp);
        float acc = 0.0f;
        for (int k = 0; k < ND; k++)
            acc = fmaf(rs[k], cp[k], acc);
        float B  = __fmul_rn(2.0f, acc);
        float t1 = __fadd_rn(S, -B);
        float d2 = __fadd_rn(t1, C);
        if (d2 < best) { best = d2; bi = c; }
    }
#pragma unroll
    for (int off = 16; off >= 1; off >>= 1) {
        float ob = __shfl_down_sync(0xffffffff, best, off);
        int   oi = __shfl_down_sync(0xffffffff, bi, off);
        if (ob < best || (ob == best && oi < bi)) { best = ob; bi = oi; }
    }
    return __shfl_sync(0xffffffff, bi, 0);
}
// --------------------------------------------------------------------

__global__ void prep_kernel(const float* __restrict__ cb) {
    int i = blockIdx.x * blockDim.x + threadIdx.x;
    const float* cp = cb + (size_t)i * ND;
    float s = 0.f;
#pragma unroll
    for (int k = 0; k < ND; k++) s = fmaf(cp[k], cp[k], s);
    g_norm[i] = s;
#pragma unroll
    for (int k = 0; k < ND; k++) {
        float v = cp[k];
        __nv_bfloat16 h = __float2bfloat16(v);
        g_cbh[(size_t)i * ND + k] = h;
        g_cbl[(size_t)i * ND + k] = __float2bfloat16(v - __bfloat162float(h));
    }
}

#define UPD2(bst, sc, bi, d, ci) \
    do { if ((d) < (bst)) { sc = bst; bst = (d); bi = (ci); } \
         else if ((d) < (sc)) { sc = (d); } } while (0)

__global__ __launch_bounds__(THREADS)
void rvq_mma_kernel(const float* __restrict__ x,
                    const float* __restrict__ cb,
                    float* __restrict__ out, int mode)
{
    extern __shared__ char smem_raw[];
    char* smem = (char*)(((uintptr_t)smem_raw + 1023) & ~(uintptr_t)1023);
    const uint32_t sb = smem_u32(smem);

    const int t = threadIdx.x, wid = t >> 5, lane = t & 31;
    const int lq = lane >> 2, lr = lane & 3;
    const long long row0 = (long long)blockIdx.x * ROWS_PER_CTA;
    float* outq = (mode == 0) ? (out + (size_t)NROWS * NQ)
                              : ((mode == 2) ? out : nullptr);

    int* s_cnt  = (int*)(smem + SM_CNT);
    int* s_rows = (int*)(smem + SM_ROWS);
    int* s_bidx = (int*)(smem + SM_BIDX);

    for (int j = 0; j < NQ; j++) {
        const float* cbj = cb + (size_t)j * NK * ND;

        // ---- A convert: r = x - q (PROVEN ops) -> bf16 hi/lo smem ----
        {
            int m = t >> 1, h = t & 1;
            const float4* xp = (const float4*)(x + (row0 + m) * ND) + h * 8;
            const float4* qp = (const float4*)(g_q + (row0 + m) * ND) + h * 8;
#pragma unroll
            for (int i = 0; i < 8; i++) {
                float4 xv = xp[i];
                float4 r;
                if (j == 0) r = xv;
                else {
                    float4 qv = qp[i];
                    r = make_float4(__fadd_rn(xv.x, -qv.x), __fadd_rn(xv.y, -qv.y),
                                    __fadd_rn(xv.z, -qv.z), __fadd_rn(xv.w, -qv.w));
                }
                __nv_bfloat162 h01 = __floats2bfloat162_rn(r.x, r.y);
                __nv_bfloat162 h23 = __floats2bfloat162_rn(r.z, r.w);
                float2 f01 = __bfloat1622float2(h01);
                float2 f23 = __bfloat1622float2(h23);
                __nv_bfloat162 l01 = __floats2bfloat162_rn(r.x - f01.x, r.y - f01.y);
                __nv_bfloat162 l23 = __floats2bfloat162_rn(r.z - f23.x, r.w - f23.y);
                uint32_t off = (uint32_t)(m * ASTRIDE + h * 64 + i * 8);
                *(uint2*)(smem + SM_A_HI + off) =
                    make_uint2(*(uint32_t*)&h01, *(uint32_t*)&h23);
                *(uint2*)(smem + SM_A_LO + off) =
                    make_uint2(*(uint32_t*)&l01, *(uint32_t*)&l23);
            }
        }
        if (t == 0) *s_cnt = 0;
        __syncthreads();

        // ---- A fragments into registers ----
        uint32_t ah[4][4], al[4][4];
        {
            int r0 = wid * 16 + lq;
            uint32_t base = (uint32_t)(r0 * ASTRIDE + lr * 4);
#pragma unroll
            for (int kc = 0; kc < 4; kc++) {
                uint32_t o = base + kc * 32;
                ah[kc][0] = *(const uint32_t*)(smem + SM_A_HI + o);
                ah[kc][1] = *(const uint32_t*)(smem + SM_A_HI + o + 8 * ASTRIDE);
                ah[kc][2] = *(const uint32_t*)(smem + SM_A_HI + o + 16);
                ah[kc][3] = *(const uint32_t*)(smem + SM_A_HI + o + 8 * ASTRIDE + 16);
                al[kc][0] = *(const uint32_t*)(smem + SM_A_LO + o);
                al[kc][1] = *(const uint32_t*)(smem + SM_A_LO + o + 8 * ASTRIDE);
                al[kc][2] = *(const uint32_t*)(smem + SM_A_LO + o + 16);
                al[kc][3] = *(const uint32_t*)(smem + SM_A_LO + o + 8 * ASTRIDE + 16);
            }
        }

        // ---- Prologue: B tile 0 (hi+lo) + norms into buf 0 ----
        {
            const __nv_bfloat16* sh = g_cbh + ((size_t)j * NK) * ND;
            const __nv_bfloat16* sl = g_cbl + ((size_t)j * NK) * ND;
#pragma unroll
            for (int i = 0; i < 4; i++) {
                int id = i * 256 + t, code = id >> 3, c8 = id & 7;
                uint32_t off = (uint32_t)(code * ASTRIDE + c8 * 16);
                cp_async16(sb + SM_B + off, sh + code * ND + c8 * 8);
                cp_async16(sb + SM_B + 18432 + off, sl + code * ND + c8 * 8);
            }
            if (t < 32)
                cp_async16(sb + SM_SN + t * 16, g_norm + j * NK + t * 4);
            asm volatile("cp.async.commit_group;" ::: "memory");
        }

        const float INF = __int_as_float(0x7f800000);
        float bA = INF, sA = INF, bB = INF, sB = INF;
        int iA = 0, iB = 0;

        for (int it = 0; it < NTILES; ++it) {
            const int buf = it & 1;
            asm volatile("cp.async.wait_group 0;" ::: "memory");
            __syncthreads();

            if (it + 1 < NTILES) {
                int nbuf = (it + 1) & 1;
                const __nv_bfloat16* sh =
                    g_cbh + ((size_t)j * NK + (it + 1) * TILE_N) * ND;
                const __nv_bfloat16* sl =
                    g_cbl + ((size_t)j * NK + (it + 1) * TILE_N) * ND;
#pragma unroll
                for (int i = 0; i < 4; i++) {
                    int id = i * 256 + t, code = id >> 3, c8 = id & 7;
                    uint32_t off = (uint32_t)(code * ASTRIDE + c8 * 16);
                    cp_async16(sb + SM_B + (uint32_t)(nbuf * 2) * 18432 + off,
                               sh + code * ND + c8 * 8);
                    cp_async16(sb + SM_B + (uint32_t)(nbuf * 2 + 1) * 18432 + off,
                               sl + code * ND + c8 * 8);
                }
                if (t < 32)
                    cp_async16(sb + SM_SN + nbuf * 512 + t * 16,
                               g_norm + j * NK + (it + 1) * TILE_N + t * 4);
            }
            asm volatile("cp.async.commit_group;" ::: "memory");

            const char* bh_p = smem + SM_B + (size_t)(buf * 2) * 18432;
            const char* bl_p = smem + SM_B + (size_t)(buf * 2 + 1) * 18432;
            const float* sn  = (const float*)(smem + SM_SN + buf * 512);

            // ---- ILP-2: two n-blocks, two independent accumulator chains ----
#pragma unroll
            for (int nb = 0; nb < 16; nb += 2) {
                float c0 = 0.f, c1 = 0.f, c2 = 0.f, c3 = 0.f;
                float d0 = 0.f, d1 = 0.f, d2r = 0.f, d3 = 0.f;
                uint32_t bo0 = (uint32_t)((nb * 8 + lq) * ASTRIDE + lr * 4);
                uint32_t bo1 = bo0 + 8 * ASTRIDE;
#pragma unroll
                for (int kc = 0; kc < 4; kc++) {
                    uint32_t o0 = bo0 + kc * 32, o1 = bo1 + kc * 32;
                    uint32_t xh0 = *(const uint32_t*)(bh_p + o0);
                    uint32_t xh1 = *(const uint32_t*)(bh_p + o0 + 16);
                    uint32_t yh0 = *(const uint32_t*)(bh_p + o1);
                    uint32_t yh1 = *(const uint32_t*)(bh_p + o1 + 16);
                    uint32_t xl0 = *(const uint32_t*)(bl_p + o0);
                    uint32_t xl1 = *(const uint32_t*)(bl_p + o0 + 16);
                    uint32_t yl0 = *(const uint32_t*)(bl_p + o1);
                    uint32_t yl1 = *(const uint32_t*)(bl_p + o1 + 16);
                    mma16816(c0, c1, c2, c3, ah[kc][0], ah[kc][1], ah[kc][2],
                             ah[kc][3], xh0, xh1);
                    mma16816(d0, d1, d2r, d3, ah[kc][0], ah[kc][1], ah[kc][2],
                             ah[kc][3], yh0, yh1);
                    mma16816(c0, c1, c2, c3, ah[kc][0], ah[kc][1], ah[kc][2],
                             ah[kc][3], xl0, xl1);
                    mma16816(d0, d1, d2r, d3, ah[kc][0], ah[kc][1], ah[kc][2],
                             ah[kc][3], yl0, yl1);
                    mma16816(c0, c1, c2, c3, al[kc][0], al[kc][1], al[kc][2],
                             al[kc][3], xh0, xh1);
                    mma16816(d0, d1, d2r, d3, al[kc][0], al[kc][1], al[kc][2],
                             al[kc][3], yh0, yh1);
                }
                int cc0 = nb * 8 + lr * 2;
                int cc1 = cc0 + 8;
                float2 n0 = *(const float2*)(sn + cc0);
                float2 n1 = *(const float2*)(sn + cc1);
                int ci0 = it * TILE_N + cc0;
                int ci1 = it * TILE_N + cc1;
                UPD2(bA, sA, iA, fmaf(-2.f, c0, n0.x), ci0);
                UPD2(bA, sA, iA, fmaf(-2.f, c1, n0.y), ci0 + 1);
                UPD2(bB, sB, iB, fmaf(-2.f, c2, n0.x), ci0);
                UPD2(bB, sB, iB, fmaf(-2.f, c3, n0.y), ci0 + 1);
                UPD2(bA, sA, iA, fmaf(-2.f, d0, n1.x), ci1);
                UPD2(bA, sA, iA, fmaf(-2.f, d1, n1.y), ci1 + 1);
                UPD2(bB, sB, iB, fmaf(-2.f, d2r, n1.x), ci1);
                UPD2(bB, sB, iB, fmaf(-2.f, d3, n1.y), ci1 + 1);
            }
        }

        // ---- quad-lane top-2 merge ----
#pragma unroll
        for (int msk = 1; msk <= 2; msk <<= 1) {
            float ob = __shfl_xor_sync(0xffffffff, bA, msk);
            int   oi = __shfl_xor_sync(0xffffffff, iA, msk);
            float os = __shfl_xor_sync(0xffffffff, sA, msk);
            if (ob < bA) { sA = fminf(bA, os); bA = ob; iA = oi; }
            else         { sA = fminf(sA, ob); }
            ob = __shfl_xor_sync(0xffffffff, bB, msk);
            oi = __shfl_xor_sync(0xffffffff, iB, msk);
            os = __shfl_xor_sync(0xffffffff, sB, msk);
            if (ob < bB) { sB = fminf(bB, os); bB = ob; iB = oi; }
            else         { sB = fminf(sB, ob); }
        }
        if (lr == 0) {
            int m0 = wid * 16 + lq;
            s_bidx[m0] = iA;
            if (sA - bA < MARGIN) { int p = atomicAdd(s_cnt, 1); s_rows[p] = m0; }
            s_bidx[m0 + 8] = iB;
            if (sB - bB < MARGIN) { int p = atomicAdd(s_cnt, 1); s_rows[p] = m0 + 8; }
        }
        __syncthreads();

        // ---- near-ties: exact warp rescan (PROVEN) ----
        int cnt = *s_cnt;
        for (int e = wid; e < cnt; e += 8) {
            int m = s_rows[e];
            int r = warp_rescan(x, j > 0, row0 + m, cbj, lane);
            if (lane == 0) s_bidx[m] = r;
        }
        __syncthreads();

        // ---- bit-exact state update + emission (PROVEN) ----
        {
            int m = t >> 1, h = t & 1;
            long long rg = row0 + m;
            int ci = s_bidx[m];
            const float4* cp = (const float4*)(cbj + (size_t)ci * ND) + h * 8;
            float4* qp = (float4*)(g_q + rg * ND) + h * 8;
#pragma unroll
            for (int i = 0; i < 8; i++) {
                float4 c4 = cp[i];
                float4 q4;
                if (j == 0) q4 = c4;
                else {
                    float4 qo = qp[i];
                    q4 = make_float4(__fadd_rn(qo.x, c4.x), __fadd_rn(qo.y, c4.y),
                                     __fadd_rn(qo.z, c4.z), __fadd_rn(qo.w, c4.w));
                }
                qp[i] = q4;
                if (j == NQ - 1 && outq)
                    (((float4*)(outq + rg * ND)) + h * 8)[i] = q4;
            }
            if (h == 0) {
                if (mode == 0)      out[rg * NQ + j] = (float)ci;
                else if (mode == 1) ((int*)out)[rg * NQ + j] = ci;
            }
        }
        __syncthreads();
    }
}

extern "C" void kernel_launch(void* const* d_in, const int* in_sizes, int n_in,
                              void* d_out, int out_size)
{
    const float* x  = (const float*)d_in[0];
    const float* cb = (const float*)d_in[1];
    if (n_in >= 2 && in_sizes[0] == NQ * NK * ND && in_sizes[1] == NROWS * ND) {
        cb = (const float*)d_in[0];
        x  = (const float*)d_in[1];
    }
    int mode = 0;
    if (out_size == NROWS * NQ)      mode = 1;
    else if (out_size == NROWS * ND) mode = 2;

    cudaFuncSetAttribute(rvq_mma_kernel,
                         cudaFuncAttributeMaxDynamicSharedMemorySize, SMEM_REQ);
    prep_kernel<<<(NQ * NK) / 256, 256>>>(cb);
    rvq_mma_kernel<<<NROWS / ROWS_PER_CTA, THREADS, SMEM_REQ>>>(
        x, cb, (float*)d_out, mode);
}

// round 15
// speedup vs baseline: 3.3687x; 1.0426x over previous
#include <cuda_runtime.h>
#include <cuda_bf16.h>
#include <cstdint>

// RVQTokenizer encode via mma.sync (HMMA) bf16-split fast path.
// R15 = R14 + split-product accumulator separation: AhBh/AhBl/AlBh each get
// their own f32 accumulator quad -> dependent HMMA chain 12 -> 4 per block,
// 12 concurrent chains/SMSP.
//
// PROVEN bit-exact decision machinery (R6..R14, rel_err = 0.0) — UNCHANGED:
//   norms : 16 strided fused-fmaf lanes, linear fold, shuffle-halves horiz
//   dot   : sequential ascending fused fmaf chain
//   d2    : fl( fl(S - 2*dot) + C ); argmin strict <, first index wins
//   state : q += cb[idx]; r = x - q (fp32 elementwise, __fadd_rn)

#define NROWS 262144
#define NQ    8
#define NK    1024
#define ND    64
#define THREADS      256
#define ROWS_PER_CTA 128
#define TILE_N       128
#define NTILES       8
#define MARGIN       2e-3f

#define ASTRIDE 144

#define SM_A_HI  0
#define SM_A_LO  18432
#define SM_B     36864
#define SM_SN    110592
#define SM_CNT   111616
#define SM_ROWS  111680
#define SM_BIDX  112192
#define SMEM_REQ (112704 + 1024)

__device__ float g_q[(size_t)NROWS * ND];
__device__ float g_norm[NQ * NK];
__device__ __nv_bfloat16 g_cbh[(size_t)NQ * NK * ND];
__device__ __nv_bfloat16 g_cbl[(size_t)NQ * NK * ND];

__device__ __forceinline__ void cp_async16(uint32_t dst, const void* src) {
    asm volatile("cp.async.cg.shared.global [%0], [%1], 16;"
                 :: "r"(dst), "l"(src));
}

static __device__ __forceinline__ uint32_t smem_u32(const void* p) {
    uint32_t a;
    asm("{ .reg .u64 t; cvta.to.shared.u64 t, %1; cvt.u32.u64 %0, t; }"
        : "=r"(a) : "l"(p));
    return a;
}

__device__ __forceinline__ void mma16816(float* c, uint32_t a0, uint32_t a1,
                                         uint32_t a2, uint32_t a3,
                                         uint32_t b0, uint32_t b1) {
    asm volatile(
        "mma.sync.aligned.m16n8k16.row.col.f32.bf16.bf16.f32 "
        "{%0,%1,%2,%3}, {%4,%5,%6,%7}, {%8,%9}, {%0,%1,%2,%3};"
        : "+f"(c[0]), "+f"(c[1]), "+f"(c[2]), "+f"(c[3])
        : "r"(a0), "r"(a1), "r"(a2), "r"(a3), "r"(b0), "r"(b1));
}

// ---------- PROVEN exact-arithmetic pieces (DO NOT CHANGE) ----------
__device__ __forceinline__ float xla_rowsum_sq16(const float* __restrict__ v) {
    float a[16];
#pragma unroll
    for (int l = 0; l < 16; l++) a[l] = 0.0f;
#pragma unroll
    for (int j = 0; j < 4; j++)
#pragma unroll
        for (int l = 0; l < 16; l++) {
            float e = v[16 * j + l];
            a[l] = fmaf(e, e, a[l]);
        }
    float c[4];
#pragma unroll
    for (int l = 0; l < 4; l++) {
        float s = __fadd_rn(a[l], a[l + 4]);
        s = __fadd_rn(s, a[l + 8]);
        c[l] = __fadd_rn(s, a[l + 12]);
    }
    return __fadd_rn(__fadd_rn(c[0], c[2]), __fadd_rn(c[1], c[3]));
}

__device__ __noinline__ int warp_rescan(const float* __restrict__ x, int use_q,
                                        long long row,
                                        const float* __restrict__ cbj, int lane)
{
    const float* xr = x + row * ND;
    const float* qr = g_q + row * ND;
    float rs[ND];
#pragma unroll
    for (int k = 0; k < ND; k++)
        rs[k] = use_q ? __fadd_rn(xr[k], -qr[k]) : xr[k];
    float S = xla_rowsum_sq16(rs);

    float best = __int_as_float(0x7f800000);
    int bi = NK;
    for (int base = 0; base < NK; base += 32) {
        int c = base + lane;
        const float* cp = cbj + (size_t)c * ND;
        float C = xla_rowsum_sq16(cp);
        float acc = 0.0f;
        for (int k = 0; k < ND; k++)
            acc = fmaf(rs[k], cp[k], acc);
        float B  = __fmul_rn(2.0f, acc);
        float t1 = __fadd_rn(S, -B);
        float d2 = __fadd_rn(t1, C);
        if (d2 < best) { best = d2; bi = c; }
    }
#pragma unroll
    for (int off = 16; off >= 1; off >>= 1) {
        float ob = __shfl_down_sync(0xffffffff, best, off);
        int   oi = __shfl_down_sync(0xffffffff, bi, off);
        if (ob < best || (ob == best && oi < bi)) { best = ob; bi = oi; }
    }
    return __shfl_sync(0xffffffff, bi, 0);
}
// --------------------------------------------------------------------

__global__ void prep_kernel(const float* __restrict__ cb) {
    int i = blockIdx.x * blockDim.x + threadIdx.x;
    const float* cp = cb + (size_t)i * ND;
    float s = 0.f;
#pragma unroll
    for (int k = 0; k < ND; k++) s = fmaf(cp[k], cp[k], s);
    g_norm[i] = s;
#pragma unroll
    for (int k = 0; k < ND; k++) {
        float v = cp[k];
        __nv_bfloat16 h = __float2bfloat16(v);
        g_cbh[(size_t)i * ND + k] = h;
        g_cbl[(size_t)i * ND + k] = __float2bfloat16(v - __bfloat162float(h));
    }
}

#define UPD2(bst, sc, bi, d, ci) \
    do { if ((d) < (bst)) { sc = bst; bst = (d); bi = (ci); } \
         else if ((d) < (sc)) { sc = (d); } } while (0)

__global__ __launch_bounds__(THREADS)
void rvq_mma_kernel(const float* __restrict__ x,
                    const float* __restrict__ cb,
                    float* __restrict__ out, int mode)
{
    extern __shared__ char smem_raw[];
    char* smem = (char*)(((uintptr_t)smem_raw + 1023) & ~(uintptr_t)1023);
    const uint32_t sb = smem_u32(smem);

    const int t = threadIdx.x, wid = t >> 5, lane = t & 31;
    const int lq = lane >> 2, lr = lane & 3;
    const long long row0 = (long long)blockIdx.x * ROWS_PER_CTA;
    float* outq = (mode == 0) ? (out + (size_t)NROWS * NQ)
                              : ((mode == 2) ? out : nullptr);

    int* s_cnt  = (int*)(smem + SM_CNT);
    int* s_rows = (int*)(smem + SM_ROWS);
    int* s_bidx = (int*)(smem + SM_BIDX);

    for (int j = 0; j < NQ; j++) {
        const float* cbj = cb + (size_t)j * NK * ND;

        // ---- A convert: r = x - q (PROVEN ops) -> bf16 hi/lo smem ----
        {
            int m = t >> 1, h = t & 1;
            const float4* xp = (const float4*)(x + (row0 + m) * ND) + h * 8;
            const float4* qp = (const float4*)(g_q + (row0 + m) * ND) + h * 8;
#pragma unroll
            for (int i = 0; i < 8; i++) {
                float4 xv = xp[i];
                float4 r;
                if (j == 0) r = xv;
                else {
                    float4 qv = qp[i];
                    r = make_float4(__fadd_rn(xv.x, -qv.x), __fadd_rn(xv.y, -qv.y),
                                    __fadd_rn(xv.z, -qv.z), __fadd_rn(xv.w, -qv.w));
                }
                __nv_bfloat162 h01 = __floats2bfloat162_rn(r.x, r.y);
                __nv_bfloat162 h23 = __floats2bfloat162_rn(r.z, r.w);
                float2 f01 = __bfloat1622float2(h01);
                float2 f23 = __bfloat1622float2(h23);
                __nv_bfloat162 l01 = __floats2bfloat162_rn(r.x - f01.x, r.y - f01.y);
                __nv_bfloat162 l23 = __floats2bfloat162_rn(r.z - f23.x, r.w - f23.y);
                uint32_t off = (uint32_t)(m * ASTRIDE + h * 64 + i * 8);
                *(uint2*)(smem + SM_A_HI + off) =
                    make_uint2(*(uint32_t*)&h01, *(uint32_t*)&h23);
                *(uint2*)(smem + SM_A_LO + off) =
                    make_uint2(*(uint32_t*)&l01, *(uint32_t*)&l23);
            }
        }
        if (t == 0) *s_cnt = 0;
        __syncthreads();

        // ---- A fragments into registers ----
        uint32_t ah[4][4], al[4][4];
        {
            int r0 = wid * 16 + lq;
            uint32_t base = (uint32_t)(r0 * ASTRIDE + lr * 4);
#pragma unroll
            for (int kc = 0; kc < 4; kc++) {
                uint32_t o = base + kc * 32;
                ah[kc][0] = *(const uint32_t*)(smem + SM_A_HI + o);
                ah[kc][1] = *(const uint32_t*)(smem + SM_A_HI + o + 8 * ASTRIDE);
                ah[kc][2] = *(const uint32_t*)(smem + SM_A_HI + o + 16);
                ah[kc][3] = *(const uint32_t*)(smem + SM_A_HI + o + 8 * ASTRIDE + 16);
                al[kc][0] = *(const uint32_t*)(smem + SM_A_LO + o);
                al[kc][1] = *(const uint32_t*)(smem + SM_A_LO + o + 8 * ASTRIDE);
                al[kc][2] = *(const uint32_t*)(smem + SM_A_LO + o + 16);
                al[kc][3] = *(const uint32_t*)(smem + SM_A_LO + o + 8 * ASTRIDE + 16);
            }
        }

        // ---- Prologue: B tile 0 (hi+lo) + norms into buf 0 ----
        {
            const __nv_bfloat16* sh = g_cbh + ((size_t)j * NK) * ND;
            const __nv_bfloat16* sl = g_cbl + ((size_t)j * NK) * ND;
#pragma unroll
            for (int i = 0; i < 4; i++) {
                int id = i * 256 + t, code = id >> 3, c8 = id & 7;
                uint32_t off = (uint32_t)(code * ASTRIDE + c8 * 16);
                cp_async16(sb + SM_B + off, sh + code * ND + c8 * 8);
                cp_async16(sb + SM_B + 18432 + off, sl + code * ND + c8 * 8);
            }
            if (t < 32)
                cp_async16(sb + SM_SN + t * 16, g_norm + j * NK + t * 4);
            asm volatile("cp.async.commit_group;" ::: "memory");
        }

        const float INF = __int_as_float(0x7f800000);
        float bA = INF, sA = INF, bB = INF, sB = INF;
        int iA = 0, iB = 0;

        for (int it = 0; it < NTILES; ++it) {
            const int buf = it & 1;
            asm volatile("cp.async.wait_group 0;" ::: "memory");
            __syncthreads();

            if (it + 1 < NTILES) {
                int nbuf = (it + 1) & 1;
                const __nv_bfloat16* sh =
                    g_cbh + ((size_t)j * NK + (it + 1) * TILE_N) * ND;
                const __nv_bfloat16* sl =
                    g_cbl + ((size_t)j * NK + (it + 1) * TILE_N) * ND;
#pragma unroll
                for (int i = 0; i < 4; i++) {
                    int id = i * 256 + t, code = id >> 3, c8 = id & 7;
                    uint32_t off = (uint32_t)(code * ASTRIDE + c8 * 16);
                    cp_async16(sb + SM_B + (uint32_t)(nbuf * 2) * 18432 + off,
                               sh + code * ND + c8 * 8);
                    cp_async16(sb + SM_B + (uint32_t)(nbuf * 2 + 1) * 18432 + off,
                               sl + code * ND + c8 * 8);
                }
                if (t < 32)
                    cp_async16(sb + SM_SN + nbuf * 512 + t * 16,
                               g_norm + j * NK + (it + 1) * TILE_N + t * 4);
            }
            asm volatile("cp.async.commit_group;" ::: "memory");

            const char* bh_p = smem + SM_B + (size_t)(buf * 2) * 18432;
            const char* bl_p = smem + SM_B + (size_t)(buf * 2 + 1) * 18432;
            const float* sn  = (const float*)(smem + SM_SN + buf * 512);

            // ---- ILP-2 x split-3: 6 independent accumulator quads ----
#pragma unroll
            for (int nb = 0; nb < 16; nb += 2) {
                float xhh[4] = {0,0,0,0}, xhl[4] = {0,0,0,0}, xlh[4] = {0,0,0,0};
                float yhh[4] = {0,0,0,0}, yhl[4] = {0,0,0,0}, ylh[4] = {0,0,0,0};
                uint32_t bo0 = (uint32_t)((nb * 8 + lq) * ASTRIDE + lr * 4);
                uint32_t bo1 = bo0 + 8 * ASTRIDE;
#pragma unroll
                for (int kc = 0; kc < 4; kc++) {
                    uint32_t o0 = bo0 + kc * 32, o1 = bo1 + kc * 32;
                    uint32_t xh0 = *(const uint32_t*)(bh_p + o0);
                    uint32_t xh1 = *(const uint32_t*)(bh_p + o0 + 16);
                    uint32_t yh0 = *(const uint32_t*)(bh_p + o1);
                    uint32_t yh1 = *(const uint32_t*)(bh_p + o1 + 16);
                    uint32_t xl0 = *(const uint32_t*)(bl_p + o0);
                    uint32_t xl1 = *(const uint32_t*)(bl_p + o0 + 16);
                    uint32_t yl0 = *(const uint32_t*)(bl_p + o1);
                    uint32_t yl1 = *(const uint32_t*)(bl_p + o1 + 16);
                    mma16816(xhh, ah[kc][0], ah[kc][1], ah[kc][2], ah[kc][3], xh0, xh1);
                    mma16816(yhh, ah[kc][0], ah[kc][1], ah[kc][2], ah[kc][3], yh0, yh1);
                    mma16816(xhl, ah[kc][0], ah[kc][1], ah[kc][2], ah[kc][3], xl0, xl1);
                    mma16816(yhl, ah[kc][0], ah[kc][1], ah[kc][2], ah[kc][3], yl0, yl1);
                    mma16816(xlh, al[kc][0], al[kc][1], al[kc][2], al[kc][3], xh0, xh1);
                    mma16816(ylh, al[kc][0], al[kc][1], al[kc][2], al[kc][3], yh0, yh1);
                }
                int cc0 = nb * 8 + lr * 2;
                int cc1 = cc0 + 8;
                float2 n0 = *(const float2*)(sn + cc0);
                float2 n1 = *(const float2*)(sn + cc1);
                int ci0 = it * TILE_N + cc0;
                int ci1 = it * TILE_N + cc1;
                float c0 = (xhh[0] + xhl[0]) + xlh[0];
                float c1 = (xhh[1] + xhl[1]) + xlh[1];
                float c2 = (xhh[2] + xhl[2]) + xlh[2];
                float c3 = (xhh[3] + xhl[3]) + xlh[3];
                float d0 = (yhh[0] + yhl[0]) + ylh[0];
                float d1 = (yhh[1] + yhl[1]) + ylh[1];
                float d2 = (yhh[2] + yhl[2]) + ylh[2];
                float d3 = (yhh[3] + yhl[3]) + ylh[3];
                UPD2(bA, sA, iA, fmaf(-2.f, c0, n0.x), ci0);
                UPD2(bA, sA, iA, fmaf(-2.f, c1, n0.y), ci0 + 1);
                UPD2(bB, sB, iB, fmaf(-2.f, c2, n0.x), ci0);
                UPD2(bB, sB, iB, fmaf(-2.f, c3, n0.y), ci0 + 1);
                UPD2(bA, sA, iA, fmaf(-2.f, d0, n1.x), ci1);
                UPD2(bA, sA, iA, fmaf(-2.f, d1, n1.y), ci1 + 1);
                UPD2(bB, sB, iB, fmaf(-2.f, d2, n1.x), ci1);
                UPD2(bB, sB, iB, fmaf(-2.f, d3, n1.y), ci1 + 1);
            }
        }

        // ---- quad-lane top-2 merge ----
#pragma unroll
        for (int msk = 1; msk <= 2; msk <<= 1) {
            float ob = __shfl_xor_sync(0xffffffff, bA, msk);
            int   oi = __shfl_xor_sync(0xffffffff, iA, msk);
            float os = __shfl_xor_sync(0xffffffff, sA, msk);
            if (ob < bA) { sA = fminf(bA, os); bA = ob; iA = oi; }
            else         { sA = fminf(sA, ob); }
            ob = __shfl_xor_sync(0xffffffff, bB, msk);
            oi = __shfl_xor_sync(0xffffffff, iB, msk);
            os = __shfl_xor_sync(0xffffffff, sB, msk);
            if (ob < bB) { sB = fminf(bB, os); bB = ob; iB = oi; }
            else         { sB = fminf(sB, ob); }
        }
        if (lr == 0) {
            int m0 = wid * 16 + lq;
            s_bidx[m0] = iA;
            if (sA - bA < MARGIN) { int p = atomicAdd(s_cnt, 1); s_rows[p] = m0; }
            s_bidx[m0 + 8] = iB;
            if (sB - bB < MARGIN) { int p = atomicAdd(s_cnt, 1); s_rows[p] = m0 + 8; }
        }
        __syncthreads();

        // ---- near-ties: exact warp rescan (PROVEN) ----
        int cnt = *s_cnt;
        for (int e = wid; e < cnt; e += 8) {
            int m = s_rows[e];
            int r = warp_rescan(x, j > 0, row0 + m, cbj, lane);
            if (lane == 0) s_bidx[m] = r;
        }
        __syncthreads();

        // ---- bit-exact state update + emission (PROVEN) ----
        {
            int m = t >> 1, h = t & 1;
            long long rg = row0 + m;
            int ci = s_bidx[m];
            const float4* cp = (const float4*)(cbj + (size_t)ci * ND) + h * 8;
            float4* qp = (float4*)(g_q + rg * ND) + h * 8;
#pragma unroll
            for (int i = 0; i < 8; i++) {
                float4 c4 = cp[i];
                float4 q4;
                if (j == 0) q4 = c4;
                else {
                    float4 qo = qp[i];
                    q4 = make_float4(__fadd_rn(qo.x, c4.x), __fadd_rn(qo.y, c4.y),
                                     __fadd_rn(qo.z, c4.z), __fadd_rn(qo.w, c4.w));
                }
                qp[i] = q4;
                if (j == NQ - 1 && outq)
                    (((float4*)(outq + rg * ND)) + h * 8)[i] = q4;
            }
            if (h == 0) {
                if (mode == 0)      out[rg * NQ + j] = (float)ci;
                else if (mode == 1) ((int*)out)[rg * NQ + j] = ci;
            }
        }
        __syncthreads();
    }
}

extern "C" void kernel_launch(void* const* d_in, const int* in_sizes, int n_in,
                              void* d_out, int out_size)
{
    const float* x  = (const float*)d_in[0];
    const float* cb = (const float*)d_in[1];
    if (n_in >= 2 && in_sizes[0] == NQ * NK * ND && in_sizes[1] == NROWS * ND) {
        cb = (const float*)d_in[0];
        x  = (const float*)d_in[1];
    }
    int mode = 0;
    if (out_size == NROWS * NQ)      mode = 1;
    else if (out_size == NROWS * ND) mode = 2;

    cudaFuncSetAttribute(rvq_mma_kernel,
                         cudaFuncAttributeMaxDynamicSharedMemorySize, SMEM_REQ);
    prep_kernel<<<(NQ * NK) / 256, 256>>>(cb);
    rvq_mma_kernel<<<NROWS / ROWS_PER_CTA, THREADS, SMEM_REQ>>>(
        x, cb, (float*)d_out, mode);
}

// round 16
// speedup vs baseline: 4.7460x; 1.4088x over previous
#include <cuda_runtime.h>
#include <cuda_bf16.h>
#include <cstdint>

// RVQTokenizer encode via mma.sync (HMMA) bf16-split fast path.
// R16 = R15 + occupancy doubling: __launch_bounds__(256,2) (128-reg cap) and
// single-buffered B smem (75KB/CTA) -> 2 CTAs/SM, 4 warps/SMSP. Inter-CTA
// overlap replaces the intra-CTA double buffer.
//
// PROVEN bit-exact decision machinery (R6..R15, rel_err = 0.0) — UNCHANGED:
//   norms : 16 strided fused-fmaf lanes, linear fold, shuffle-halves horiz
//   dot   : sequential ascending fused fmaf chain
//   d2    : fl( fl(S - 2*dot) + C ); argmin strict <, first index wins
//   state : q += cb[idx]; r = x - q (fp32 elementwise, __fadd_rn)

#define NROWS 262144
#define NQ    8
#define NK    1024
#define ND    64
#define THREADS      256
#define ROWS_PER_CTA 128
#define TILE_N       128
#define NTILES       8
#define MARGIN       2e-3f

#define ASTRIDE 144

#define SM_A_HI  0
#define SM_A_LO  18432
#define SM_B     36864           // hi at +0, lo at +18432 (single buffer)
#define SM_SN    73728           // 512 B norms
#define SM_CNT   74240
#define SM_ROWS  74304
#define SM_BIDX  74816
#define SMEM_REQ 75328

__device__ float g_q[(size_t)NROWS * ND];
__device__ float g_norm[NQ * NK];
__device__ __nv_bfloat16 g_cbh[(size_t)NQ * NK * ND];
__device__ __nv_bfloat16 g_cbl[(size_t)NQ * NK * ND];

__device__ __forceinline__ void cp_async16(uint32_t dst, const void* src) {
    asm volatile("cp.async.cg.shared.global [%0], [%1], 16;"
                 :: "r"(dst), "l"(src));
}

static __device__ __forceinline__ uint32_t smem_u32(const void* p) {
    uint32_t a;
    asm("{ .reg .u64 t; cvta.to.shared.u64 t, %1; cvt.u32.u64 %0, t; }"
        : "=r"(a) : "l"(p));
    return a;
}

__device__ __forceinline__ void mma16816(float* c, uint32_t a0, uint32_t a1,
                                         uint32_t a2, uint32_t a3,
                                         uint32_t b0, uint32_t b1) {
    asm volatile(
        "mma.sync.aligned.m16n8k16.row.col.f32.bf16.bf16.f32 "
        "{%0,%1,%2,%3}, {%4,%5,%6,%7}, {%8,%9}, {%0,%1,%2,%3};"
        : "+f"(c[0]), "+f"(c[1]), "+f"(c[2]), "+f"(c[3])
        : "r"(a0), "r"(a1), "r"(a2), "r"(a3), "r"(b0), "r"(b1));
}

// ---------- PROVEN exact-arithmetic pieces (DO NOT CHANGE) ----------
__device__ __forceinline__ float xla_rowsum_sq16(const float* __restrict__ v) {
    float a[16];
#pragma unroll
    for (int l = 0; l < 16; l++) a[l] = 0.0f;
#pragma unroll
    for (int j = 0; j < 4; j++)
#pragma unroll
        for (int l = 0; l < 16; l++) {
            float e = v[16 * j + l];
            a[l] = fmaf(e, e, a[l]);
        }
    float c[4];
#pragma unroll
    for (int l = 0; l < 4; l++) {
        float s = __fadd_rn(a[l], a[l + 4]);
        s = __fadd_rn(s, a[l + 8]);
        c[l] = __fadd_rn(s, a[l + 12]);
    }
    return __fadd_rn(__fadd_rn(c[0], c[2]), __fadd_rn(c[1], c[3]));
}

__device__ __noinline__ int warp_rescan(const float* __restrict__ x, int use_q,
                                        long long row,
                                        const float* __restrict__ cbj, int lane)
{
    const float* xr = x + row * ND;
    const float* qr = g_q + row * ND;
    float rs[ND];
#pragma unroll
    for (int k = 0; k < ND; k++)
        rs[k] = use_q ? __fadd_rn(xr[k], -qr[k]) : xr[k];
    float S = xla_rowsum_sq16(rs);

    float best = __int_as_float(0x7f800000);
    int bi = NK;
    for (int base = 0; base < NK; base += 32) {
        int c = base + lane;
        const float* cp = cbj + (size_t)c * ND;
        float C = xla_rowsum_sq16(cp);
        float acc = 0.0f;
        for (int k = 0; k < ND; k++)
            acc = fmaf(rs[k], cp[k], acc);
        float B  = __fmul_rn(2.0f, acc);
        float t1 = __fadd_rn(S, -B);
        float d2 = __fadd_rn(t1, C);
        if (d2 < best) { best = d2; bi = c; }
    }
#pragma unroll
    for (int off = 16; off >= 1; off >>= 1) {
        float ob = __shfl_down_sync(0xffffffff, best, off);
        int   oi = __shfl_down_sync(0xffffffff, bi, off);
        if (ob < best || (ob == best && oi < bi)) { best = ob; bi = oi; }
    }
    return __shfl_sync(0xffffffff, bi, 0);
}
// --------------------------------------------------------------------

__global__ void prep_kernel(const float* __restrict__ cb) {
    int i = blockIdx.x * blockDim.x + threadIdx.x;
    const float* cp = cb + (size_t)i * ND;
    float s = 0.f;
#pragma unroll
    for (int k = 0; k < ND; k++) s = fmaf(cp[k], cp[k], s);
    g_norm[i] = s;
#pragma unroll
    for (int k = 0; k < ND; k++) {
        float v = cp[k];
        __nv_bfloat16 h = __float2bfloat16(v);
        g_cbh[(size_t)i * ND + k] = h;
        g_cbl[(size_t)i * ND + k] = __float2bfloat16(v - __bfloat162float(h));
    }
}

#define UPD2(bst, sc, bi, d, ci) \
    do { if ((d) < (bst)) { sc = bst; bst = (d); bi = (ci); } \
         else if ((d) < (sc)) { sc = (d); } } while (0)

__global__ __launch_bounds__(THREADS, 2)
void rvq_mma_kernel(const float* __restrict__ x,
                    const float* __restrict__ cb,
                    float* __restrict__ out, int mode)
{
    extern __shared__ __align__(16) char smem[];
    const uint32_t sb = smem_u32(smem);

    const int t = threadIdx.x, wid = t >> 5, lane = t & 31;
    const int lq = lane >> 2, lr = lane & 3;
    const long long row0 = (long long)blockIdx.x * ROWS_PER_CTA;
    float* outq = (mode == 0) ? (out + (size_t)NROWS * NQ)
                              : ((mode == 2) ? out : nullptr);

    int* s_cnt  = (int*)(smem + SM_CNT);
    int* s_rows = (int*)(smem + SM_ROWS);
    int* s_bidx = (int*)(smem + SM_BIDX);

    for (int j = 0; j < NQ; j++) {
        const float* cbj = cb + (size_t)j * NK * ND;

        // ---- A convert: r = x - q (PROVEN ops) -> bf16 hi/lo smem ----
        {
            int m = t >> 1, h = t & 1;
            const float4* xp = (const float4*)(x + (row0 + m) * ND) + h * 8;
            const float4* qp = (const float4*)(g_q + (row0 + m) * ND) + h * 8;
#pragma unroll
            for (int i = 0; i < 8; i++) {
                float4 xv = xp[i];
                float4 r;
                if (j == 0) r = xv;
                else {
                    float4 qv = qp[i];
                    r = make_float4(__fadd_rn(xv.x, -qv.x), __fadd_rn(xv.y, -qv.y),
                                    __fadd_rn(xv.z, -qv.z), __fadd_rn(xv.w, -qv.w));
                }
                __nv_bfloat162 h01 = __floats2bfloat162_rn(r.x, r.y);
                __nv_bfloat162 h23 = __floats2bfloat162_rn(r.z, r.w);
                float2 f01 = __bfloat1622float2(h01);
                float2 f23 = __bfloat1622float2(h23);
                __nv_bfloat162 l01 = __floats2bfloat162_rn(r.x - f01.x, r.y - f01.y);
                __nv_bfloat162 l23 = __floats2bfloat162_rn(r.z - f23.x, r.w - f23.y);
                uint32_t off = (uint32_t)(m * ASTRIDE + h * 64 + i * 8);
                *(uint2*)(smem + SM_A_HI + off) =
                    make_uint2(*(uint32_t*)&h01, *(uint32_t*)&h23);
                *(uint2*)(smem + SM_A_LO + off) =
                    make_uint2(*(uint32_t*)&l01, *(uint32_t*)&l23);
            }
        }
        if (t == 0) *s_cnt = 0;
        __syncthreads();

        // ---- A fragments into registers (persist across tiles) ----
        uint32_t ah[4][4], al[4][4];
        {
            int r0 = wid * 16 + lq;
            uint32_t base = (uint32_t)(r0 * ASTRIDE + lr * 4);
#pragma unroll
            for (int kc = 0; kc < 4; kc++) {
                uint32_t o = base + kc * 32;
                ah[kc][0] = *(const uint32_t*)(smem + SM_A_HI + o);
                ah[kc][1] = *(const uint32_t*)(smem + SM_A_HI + o + 8 * ASTRIDE);
                ah[kc][2] = *(const uint32_t*)(smem + SM_A_HI + o + 16);
                ah[kc][3] = *(const uint32_t*)(smem + SM_A_HI + o + 8 * ASTRIDE + 16);
                al[kc][0] = *(const uint32_t*)(smem + SM_A_LO + o);
                al[kc][1] = *(const uint32_t*)(smem + SM_A_LO + o + 8 * ASTRIDE);
                al[kc][2] = *(const uint32_t*)(smem + SM_A_LO + o + 16);
                al[kc][3] = *(const uint32_t*)(smem + SM_A_LO + o + 8 * ASTRIDE + 16);
            }
        }

        const float INF = __int_as_float(0x7f800000);
        float bA = INF, sA = INF, bB = INF, sB = INF;
        int iA = 0, iB = 0;

        for (int it = 0; it < NTILES; ++it) {
            // Single-buffer B: all warps done with previous tile before refill.
            __syncthreads();
            {
                const __nv_bfloat16* sh =
                    g_cbh + ((size_t)j * NK + it * TILE_N) * ND;
                const __nv_bfloat16* sl =
                    g_cbl + ((size_t)j * NK + it * TILE_N) * ND;
#pragma unroll
                for (int i = 0; i < 4; i++) {
                    int id = i * 256 + t, code = id >> 3, c8 = id & 7;
                    uint32_t off = (uint32_t)(code * ASTRIDE + c8 * 16);
                    cp_async16(sb + SM_B + off, sh + code * ND + c8 * 8);
                    cp_async16(sb + SM_B + 18432 + off, sl + code * ND + c8 * 8);
                }
                if (t < 32)
                    cp_async16(sb + SM_SN + t * 16,
                               g_norm + j * NK + it * TILE_N + t * 4);
                asm volatile("cp.async.commit_group;" ::: "memory");
                asm volatile("cp.async.wait_group 0;" ::: "memory");
            }
            __syncthreads();

            const char* bh_p = smem + SM_B;
            const char* bl_p = smem + SM_B + 18432;
            const float* sn  = (const float*)(smem + SM_SN);

            // ---- ILP-2 x split-3: 6 independent accumulator quads ----
#pragma unroll
            for (int nb = 0; nb < 16; nb += 2) {
                float xhh[4] = {0,0,0,0}, xhl[4] = {0,0,0,0}, xlh[4] = {0,0,0,0};
                float yhh[4] = {0,0,0,0}, yhl[4] = {0,0,0,0}, ylh[4] = {0,0,0,0};
                uint32_t bo0 = (uint32_t)((nb * 8 + lq) * ASTRIDE + lr * 4);
                uint32_t bo1 = bo0 + 8 * ASTRIDE;
#pragma unroll
                for (int kc = 0; kc < 4; kc++) {
                    uint32_t o0 = bo0 + kc * 32, o1 = bo1 + kc * 32;
                    uint32_t xh0 = *(const uint32_t*)(bh_p + o0);
                    uint32_t xh1 = *(const uint32_t*)(bh_p + o0 + 16);
                    uint32_t yh0 = *(const uint32_t*)(bh_p + o1);
                    uint32_t yh1 = *(const uint32_t*)(bh_p + o1 + 16);
                    uint32_t xl0 = *(const uint32_t*)(bl_p + o0);
                    uint32_t xl1 = *(const uint32_t*)(bl_p + o0 + 16);
                    uint32_t yl0 = *(const uint32_t*)(bl_p + o1);
                    uint32_t yl1 = *(const uint32_t*)(bl_p + o1 + 16);
                    mma16816(xhh, ah[kc][0], ah[kc][1], ah[kc][2], ah[kc][3], xh0, xh1);
                    mma16816(yhh, ah[kc][0], ah[kc][1], ah[kc][2], ah[kc][3], yh0, yh1);
                    mma16816(xhl, ah[kc][0], ah[kc][1], ah[kc][2], ah[kc][3], xl0, xl1);
                    mma16816(yhl, ah[kc][0], ah[kc][1], ah[kc][2], ah[kc][3], yl0, yl1);
                    mma16816(xlh, al[kc][0], al[kc][1], al[kc][2], al[kc][3], xh0, xh1);
                    mma16816(ylh, al[kc][0], al[kc][1], al[kc][2], al[kc][3], yh0, yh1);
                }
                int cc0 = nb * 8 + lr * 2;
                int cc1 = cc0 + 8;
                float2 n0 = *(const float2*)(sn + cc0);
                float2 n1 = *(const float2*)(sn + cc1);
                int ci0 = it * TILE_N + cc0;
                int ci1 = it * TILE_N + cc1;
                float c0 = (xhh[0] + xhl[0]) + xlh[0];
                float c1 = (xhh[1] + xhl[1]) + xlh[1];
                float c2 = (xhh[2] + xhl[2]) + xlh[2];
                float c3 = (xhh[3] + xhl[3]) + xlh[3];
                float d0 = (yhh[0] + yhl[0]) + ylh[0];
                float d1 = (yhh[1] + yhl[1]) + ylh[1];
                float d2 = (yhh[2] + yhl[2]) + ylh[2];
                float d3 = (yhh[3] + yhl[3]) + ylh[3];
                UPD2(bA, sA, iA, fmaf(-2.f, c0, n0.x), ci0);
                UPD2(bA, sA, iA, fmaf(-2.f, c1, n0.y), ci0 + 1);
                UPD2(bB, sB, iB, fmaf(-2.f, c2, n0.x), ci0);
                UPD2(bB, sB, iB, fmaf(-2.f, c3, n0.y), ci0 + 1);
                UPD2(bA, sA, iA, fmaf(-2.f, d0, n1.x), ci1);
                UPD2(bA, sA, iA, fmaf(-2.f, d1, n1.y), ci1 + 1);
                UPD2(bB, sB, iB, fmaf(-2.f, d2, n1.x), ci1);
                UPD2(bB, sB, iB, fmaf(-2.f, d3, n1.y), ci1 + 1);
            }
        }

        // ---- quad-lane top-2 merge ----
#pragma unroll
        for (int msk = 1; msk <= 2; msk <<= 1) {
            float ob = __shfl_xor_sync(0xffffffff, bA, msk);
            int   oi = __shfl_xor_sync(0xffffffff, iA, msk);
            float os = __shfl_xor_sync(0xffffffff, sA, msk);
            if (ob < bA) { sA = fminf(bA, os); bA = ob; iA = oi; }
            else         { sA = fminf(sA, ob); }
            ob = __shfl_xor_sync(0xffffffff, bB, msk);
            oi = __shfl_xor_sync(0xffffffff, iB, msk);
            os = __shfl_xor_sync(0xffffffff, sB, msk);
            if (ob < bB) { sB = fminf(bB, os); bB = ob; iB = oi; }
            else         { sB = fminf(sB, ob); }
        }
        if (lr == 0) {
            int m0 = wid * 16 + lq;
            s_bidx[m0] = iA;
            if (sA - bA < MARGIN) { int p = atomicAdd(s_cnt, 1); s_rows[p] = m0; }
            s_bidx[m0 + 8] = iB;
            if (sB - bB < MARGIN) { int p = atomicAdd(s_cnt, 1); s_rows[p] = m0 + 8; }
        }
        __syncthreads();

        // ---- near-ties: exact warp rescan (PROVEN) ----
        int cnt = *s_cnt;
        for (int e = wid; e < cnt; e += 8) {
            int m = s_rows[e];
            int r = warp_rescan(x, j > 0, row0 + m, cbj, lane);
            if (lane == 0) s_bidx[m] = r;
        }
        __syncthreads();

        // ---- bit-exact state update + emission (PROVEN) ----
        {
            int m = t >> 1, h = t & 1;
            long long rg = row0 + m;
            int ci = s_bidx[m];
            const float4* cp = (const float4*)(cbj + (size_t)ci * ND) + h * 8;
            float4* qp = (float4*)(g_q + rg * ND) + h * 8;
#pragma unroll
            for (int i = 0; i < 8; i++) {
                float4 c4 = cp[i];
                float4 q4;
                if (j == 0) q4 = c4;
                else {
                    float4 qo = qp[i];
                    q4 = make_float4(__fadd_rn(qo.x, c4.x), __fadd_rn(qo.y, c4.y),
                                     __fadd_rn(qo.z, c4.z), __fadd_rn(qo.w, c4.w));
                }
                qp[i] = q4;
                if (j == NQ - 1 && outq)
                    (((float4*)(outq + rg * ND)) + h * 8)[i] = q4;
            }
            if (h == 0) {
                if (mode == 0)      out[rg * NQ + j] = (float)ci;
                else if (mode == 1) ((int*)out)[rg * NQ + j] = ci;
            }
        }
        __syncthreads();
    }
}

extern "C" void kernel_launch(void* const* d_in, const int* in_sizes, int n_in,
                              void* d_out, int out_size)
{
    const float* x  = (const float*)d_in[0];
    const float* cb = (const float*)d_in[1];
    if (n_in >= 2 && in_sizes[0] == NQ * NK * ND && in_sizes[1] == NROWS * ND) {
        cb = (const float*)d_in[0];
        x  = (const float*)d_in[1];
    }
    int mode = 0;
    if (out_size == NROWS * NQ)      mode = 1;
    else if (out_size == NROWS * ND) mode = 2;

    cudaFuncSetAttribute(rvq_mma_kernel,
                         cudaFuncAttributeMaxDynamicSharedMemorySize, SMEM_REQ);
    prep_kernel<<<(NQ * NK) / 256, 256>>>(cb);
    rvq_mma_kernel<<<NROWS / ROWS_PER_CTA, THREADS, SMEM_REQ>>>(
        x, cb, (float*)d_out, mode);
}

// round 17
// speedup vs baseline: 4.9363x; 1.0401x over previous
#include <cuda_runtime.h>
#include <cuda_bf16.h>
#include <cstdint>

// RVQTokenizer encode via mma.sync (HMMA) bf16-split fast path.
// R17 = R16 + third CTA/SM: __launch_bounds__(256,3) (85-reg cap), ILP-1
// (3 accumulator quads) to fit regs. 6 warps/SMSP, 18 concurrent HMMA chains.
//
// PROVEN bit-exact decision machinery (R6..R16, rel_err = 0.0) — UNCHANGED:
//   norms : 16 strided fused-fmaf lanes, linear fold, shuffle-halves horiz
//   dot   : sequential ascending fused fmaf chain
//   d2    : fl( fl(S - 2*dot) + C ); argmin strict <, first index wins
//   state : q += cb[idx]; r = x - q (fp32 elementwise, __fadd_rn)

#define NROWS 262144
#define NQ    8
#define NK    1024
#define ND    64
#define THREADS      256
#define ROWS_PER_CTA 128
#define TILE_N       128
#define NTILES       8
#define MARGIN       2e-3f

#define ASTRIDE 144

#define SM_A_HI  0
#define SM_A_LO  18432
#define SM_B     36864           // hi at +0, lo at +18432 (single buffer)
#define SM_SN    73728
#define SM_CNT   74240
#define SM_ROWS  74304
#define SM_BIDX  74816
#define SMEM_REQ 75328           // x3 CTAs = 225.98 KB <= 228 KB carveout

__device__ float g_q[(size_t)NROWS * ND];
__device__ float g_norm[NQ * NK];
__device__ __nv_bfloat16 g_cbh[(size_t)NQ * NK * ND];
__device__ __nv_bfloat16 g_cbl[(size_t)NQ * NK * ND];

__device__ __forceinline__ void cp_async16(uint32_t dst, const void* src) {
    asm volatile("cp.async.cg.shared.global [%0], [%1], 16;"
                 :: "r"(dst), "l"(src));
}

static __device__ __forceinline__ uint32_t smem_u32(const void* p) {
    uint32_t a;
    asm("{ .reg .u64 t; cvta.to.shared.u64 t, %1; cvt.u32.u64 %0, t; }"
        : "=r"(a) : "l"(p));
    return a;
}

__device__ __forceinline__ void mma16816(float* c, uint32_t a0, uint32_t a1,
                                         uint32_t a2, uint32_t a3,
                                         uint32_t b0, uint32_t b1) {
    asm volatile(
        "mma.sync.aligned.m16n8k16.row.col.f32.bf16.bf16.f32 "
        "{%0,%1,%2,%3}, {%4,%5,%6,%7}, {%8,%9}, {%0,%1,%2,%3};"
        : "+f"(c[0]), "+f"(c[1]), "+f"(c[2]), "+f"(c[3])
        : "r"(a0), "r"(a1), "r"(a2), "r"(a3), "r"(b0), "r"(b1));
}

// ---------- PROVEN exact-arithmetic pieces (DO NOT CHANGE) ----------
__device__ __forceinline__ float xla_rowsum_sq16(const float* __restrict__ v) {
    float a[16];
#pragma unroll
    for (int l = 0; l < 16; l++) a[l] = 0.0f;
#pragma unroll
    for (int j = 0; j < 4; j++)
#pragma unroll
        for (int l = 0; l < 16; l++) {
            float e = v[16 * j + l];
            a[l] = fmaf(e, e, a[l]);
        }
    float c[4];
#pragma unroll
    for (int l = 0; l < 4; l++) {
        float s = __fadd_rn(a[l], a[l + 4]);
        s = __fadd_rn(s, a[l + 8]);
        c[l] = __fadd_rn(s, a[l + 12]);
    }
    return __fadd_rn(__fadd_rn(c[0], c[2]), __fadd_rn(c[1], c[3]));
}

__device__ __noinline__ int warp_rescan(const float* __restrict__ x, int use_q,
                                        long long row,
                                        const float* __restrict__ cbj, int lane)
{
    const float* xr = x + row * ND;
    const float* qr = g_q + row * ND;
    float rs[ND];
#pragma unroll
    for (int k = 0; k < ND; k++)
        rs[k] = use_q ? __fadd_rn(xr[k], -qr[k]) : xr[k];
    float S = xla_rowsum_sq16(rs);

    float best = __int_as_float(0x7f800000);
    int bi = NK;
    for (int base = 0; base < NK; base += 32) {
        int c = base + lane;
        const float* cp = cbj + (size_t)c * ND;
        float C = xla_rowsum_sq16(cp);
        float acc = 0.0f;
        for (int k = 0; k < ND; k++)
            acc = fmaf(rs[k], cp[k], acc);
        float B  = __fmul_rn(2.0f, acc);
        float t1 = __fadd_rn(S, -B);
        float d2 = __fadd_rn(t1, C);
        if (d2 < best) { best = d2; bi = c; }
    }
#pragma unroll
    for (int off = 16; off >= 1; off >>= 1) {
        float ob = __shfl_down_sync(0xffffffff, best, off);
        int   oi = __shfl_down_sync(0xffffffff, bi, off);
        if (ob < best || (ob == best && oi < bi)) { best = ob; bi = oi; }
    }
    return __shfl_sync(0xffffffff, bi, 0);
}
// --------------------------------------------------------------------

__global__ void prep_kernel(const float* __restrict__ cb) {
    int i = blockIdx.x * blockDim.x + threadIdx.x;
    const float* cp = cb + (size_t)i * ND;
    float s = 0.f;
#pragma unroll
    for (int k = 0; k < ND; k++) s = fmaf(cp[k], cp[k], s);
    g_norm[i] = s;
#pragma unroll
    for (int k = 0; k < ND; k++) {
        float v = cp[k];
        __nv_bfloat16 h = __float2bfloat16(v);
        g_cbh[(size_t)i * ND + k] = h;
        g_cbl[(size_t)i * ND + k] = __float2bfloat16(v - __bfloat162float(h));
    }
}

#define UPD2(bst, sc, bi, d, ci) \
    do { if ((d) < (bst)) { sc = bst; bst = (d); bi = (ci); } \
         else if ((d) < (sc)) { sc = (d); } } while (0)

__global__ __launch_bounds__(THREADS, 3)
void rvq_mma_kernel(const float* __restrict__ x,
                    const float* __restrict__ cb,
                    float* __restrict__ out, int mode)
{
    extern __shared__ __align__(16) char smem[];
    const uint32_t sb = smem_u32(smem);

    const int t = threadIdx.x, wid = t >> 5, lane = t & 31;
    const int lq = lane >> 2, lr = lane & 3;
    const long long row0 = (long long)blockIdx.x * ROWS_PER_CTA;
    float* outq = (mode == 0) ? (out + (size_t)NROWS * NQ)
                              : ((mode == 2) ? out : nullptr);

    int* s_cnt  = (int*)(smem + SM_CNT);
    int* s_rows = (int*)(smem + SM_ROWS);
    int* s_bidx = (int*)(smem + SM_BIDX);

    for (int j = 0; j < NQ; j++) {
        const float* cbj = cb + (size_t)j * NK * ND;

        // ---- A convert: r = x - q (PROVEN ops) -> bf16 hi/lo smem ----
        {
            int m = t >> 1, h = t & 1;
            const float4* xp = (const float4*)(x + (row0 + m) * ND) + h * 8;
            const float4* qp = (const float4*)(g_q + (row0 + m) * ND) + h * 8;
#pragma unroll
            for (int i = 0; i < 8; i++) {
                float4 xv = xp[i];
                float4 r;
                if (j == 0) r = xv;
                else {
                    float4 qv = qp[i];
                    r = make_float4(__fadd_rn(xv.x, -qv.x), __fadd_rn(xv.y, -qv.y),
                                    __fadd_rn(xv.z, -qv.z), __fadd_rn(xv.w, -qv.w));
                }
                __nv_bfloat162 h01 = __floats2bfloat162_rn(r.x, r.y);
                __nv_bfloat162 h23 = __floats2bfloat162_rn(r.z, r.w);
                float2 f01 = __bfloat1622float2(h01);
                float2 f23 = __bfloat1622float2(h23);
                __nv_bfloat162 l01 = __floats2bfloat162_rn(r.x - f01.x, r.y - f01.y);
                __nv_bfloat162 l23 = __floats2bfloat162_rn(r.z - f23.x, r.w - f23.y);
                uint32_t off = (uint32_t)(m * ASTRIDE + h * 64 + i * 8);
                *(uint2*)(smem + SM_A_HI + off) =
                    make_uint2(*(uint32_t*)&h01, *(uint32_t*)&h23);
                *(uint2*)(smem + SM_A_LO + off) =
                    make_uint2(*(uint32_t*)&l01, *(uint32_t*)&l23);
            }
        }
        if (t == 0) *s_cnt = 0;
        __syncthreads();

        // ---- A fragments into registers (persist across tiles) ----
        uint32_t ah[4][4], al[4][4];
        {
            int r0 = wid * 16 + lq;
            uint32_t base = (uint32_t)(r0 * ASTRIDE + lr * 4);
#pragma unroll
            for (int kc = 0; kc < 4; kc++) {
                uint32_t o = base + kc * 32;
                ah[kc][0] = *(const uint32_t*)(smem + SM_A_HI + o);
                ah[kc][1] = *(const uint32_t*)(smem + SM_A_HI + o + 8 * ASTRIDE);
                ah[kc][2] = *(const uint32_t*)(smem + SM_A_HI + o + 16);
                ah[kc][3] = *(const uint32_t*)(smem + SM_A_HI + o + 8 * ASTRIDE + 16);
                al[kc][0] = *(const uint32_t*)(smem + SM_A_LO + o);
                al[kc][1] = *(const uint32_t*)(smem + SM_A_LO + o + 8 * ASTRIDE);
                al[kc][2] = *(const uint32_t*)(smem + SM_A_LO + o + 16);
                al[kc][3] = *(const uint32_t*)(smem + SM_A_LO + o + 8 * ASTRIDE + 16);
            }
        }

        const float INF = __int_as_float(0x7f800000);
        float bA = INF, sA = INF, bB = INF, sB = INF;
        int iA = 0, iB = 0;

        for (int it = 0; it < NTILES; ++it) {
            __syncthreads();
            {
                const __nv_bfloat16* sh =
                    g_cbh + ((size_t)j * NK + it * TILE_N) * ND;
                const __nv_bfloat16* sl =
                    g_cbl + ((size_t)j * NK + it * TILE_N) * ND;
#pragma unroll
                for (int i = 0; i < 4; i++) {
                    int id = i * 256 + t, code = id >> 3, c8 = id & 7;
                    uint32_t off = (uint32_t)(code * ASTRIDE + c8 * 16);
                    cp_async16(sb + SM_B + off, sh + code * ND + c8 * 8);
                    cp_async16(sb + SM_B + 18432 + off, sl + code * ND + c8 * 8);
                }
                if (t < 32)
                    cp_async16(sb + SM_SN + t * 16,
                               g_norm + j * NK + it * TILE_N + t * 4);
                asm volatile("cp.async.commit_group;" ::: "memory");
                asm volatile("cp.async.wait_group 0;" ::: "memory");
            }
            __syncthreads();

            const char* bh_p = smem + SM_B;
            const char* bl_p = smem + SM_B + 18432;
            const float* sn  = (const float*)(smem + SM_SN);

            // ---- ILP-1 x split-3: 3 independent accumulator quads ----
#pragma unroll
            for (int nb = 0; nb < 16; nb++) {
                float chh[4] = {0,0,0,0}, chl[4] = {0,0,0,0}, clh[4] = {0,0,0,0};
                uint32_t bo = (uint32_t)((nb * 8 + lq) * ASTRIDE + lr * 4);
#pragma unroll
                for (int kc = 0; kc < 4; kc++) {
                    uint32_t o = bo + kc * 32;
                    uint32_t bh0 = *(const uint32_t*)(bh_p + o);
                    uint32_t bh1 = *(const uint32_t*)(bh_p + o + 16);
                    uint32_t bl0 = *(const uint32_t*)(bl_p + o);
                    uint32_t bl1 = *(const uint32_t*)(bl_p + o + 16);
                    mma16816(chh, ah[kc][0], ah[kc][1], ah[kc][2], ah[kc][3], bh0, bh1);
                    mma16816(chl, ah[kc][0], ah[kc][1], ah[kc][2], ah[kc][3], bl0, bl1);
                    mma16816(clh, al[kc][0], al[kc][1], al[kc][2], al[kc][3], bh0, bh1);
                }
                int cc = nb * 8 + lr * 2;
                float2 nv = *(const float2*)(sn + cc);
                int ci = it * TILE_N + cc;
                float c0 = (chh[0] + chl[0]) + clh[0];
                float c1 = (chh[1] + chl[1]) + clh[1];
                float c2 = (chh[2] + chl[2]) + clh[2];
                float c3 = (chh[3] + chl[3]) + clh[3];
                UPD2(bA, sA, iA, fmaf(-2.f, c0, nv.x), ci);
                UPD2(bA, sA, iA, fmaf(-2.f, c1, nv.y), ci + 1);
                UPD2(bB, sB, iB, fmaf(-2.f, c2, nv.x), ci);
                UPD2(bB, sB, iB, fmaf(-2.f, c3, nv.y), ci + 1);
            }
        }

        // ---- quad-lane top-2 merge ----
#pragma unroll
        for (int msk = 1; msk <= 2; msk <<= 1) {
            float ob = __shfl_xor_sync(0xffffffff, bA, msk);
            int   oi = __shfl_xor_sync(0xffffffff, iA, msk);
            float os = __shfl_xor_sync(0xffffffff, sA, msk);
            if (ob < bA) { sA = fminf(bA, os); bA = ob; iA = oi; }
            else         { sA = fminf(sA, ob); }
            ob = __shfl_xor_sync(0xffffffff, bB, msk);
            oi = __shfl_xor_sync(0xffffffff, iB, msk);
            os = __shfl_xor_sync(0xffffffff, sB, msk);
            if (ob < bB) { sB = fminf(bB, os); bB = ob; iB = oi; }
            else         { sB = fminf(sB, ob); }
        }
        if (lr == 0) {
            int m0 = wid * 16 + lq;
            s_bidx[m0] = iA;
            if (sA - bA < MARGIN) { int p = atomicAdd(s_cnt, 1); s_rows[p] = m0; }
            s_bidx[m0 + 8] = iB;
            if (sB - bB < MARGIN) { int p = atomicAdd(s_cnt, 1); s_rows[p] = m0 + 8; }
        }
        __syncthreads();

        // ---- near-ties: exact warp rescan (PROVEN) ----
        int cnt = *s_cnt;
        for (int e = wid; e < cnt; e += 8) {
            int m = s_rows[e];
            int r = warp_rescan(x, j > 0, row0 + m, cbj, lane);
            if (lane == 0) s_bidx[m] = r;
        }
        __syncthreads();

        // ---- bit-exact state update + emission (PROVEN) ----
        {
            int m = t >> 1, h = t & 1;
            long long rg = row0 + m;
            int ci = s_bidx[m];
            const float4* cp = (const float4*)(cbj + (size_t)ci * ND) + h * 8;
            float4* qp = (float4*)(g_q + rg * ND) + h * 8;
#pragma unroll
            for (int i = 0; i < 8; i++) {
                float4 c4 = cp[i];
                float4 q4;
                if (j == 0) q4 = c4;
                else {
                    float4 qo = qp[i];
                    q4 = make_float4(__fadd_rn(qo.x, c4.x), __fadd_rn(qo.y, c4.y),
                                     __fadd_rn(qo.z, c4.z), __fadd_rn(qo.w, c4.w));
                }
                qp[i] = q4;
                if (j == NQ - 1 && outq)
                    (((float4*)(outq + rg * ND)) + h * 8)[i] = q4;
            }
            if (h == 0) {
                if (mode == 0)      out[rg * NQ + j] = (float)ci;
                else if (mode == 1) ((int*)out)[rg * NQ + j] = ci;
            }
        }
        __syncthreads();
    }
}

extern "C" void kernel_launch(void* const* d_in, const int* in_sizes, int n_in,
                              void* d_out, int out_size)
{
    const float* x  = (const float*)d_in[0];
    const float* cb = (const float*)d_in[1];
    if (n_in >= 2 && in_sizes[0] == NQ * NK * ND && in_sizes[1] == NROWS * ND) {
        cb = (const float*)d_in[0];
        x  = (const float*)d_in[1];
    }
    int mode = 0;
    if (out_size == NROWS * NQ)      mode = 1;
    else if (out_size == NROWS * ND) mode = 2;

    cudaFuncSetAttribute(rvq_mma_kernel,
                         cudaFuncAttributeMaxDynamicSharedMemorySize, SMEM_REQ);
    prep_kernel<<<(NQ * NK) / 256, 256>>>(cb);
    rvq_mma_kernel<<<NROWS / ROWS_PER_CTA, THREADS, SMEM_REQ>>>(
        x, cb, (float*)d_out, mode);
}